// round 1
// baseline (speedup 1.0000x reference)
#include <cuda_runtime.h>
#include <math.h>

#define BATCH   8
#define NSEQ    1024
#define DIM     1024
#define HEADS   16
#define DHEAD   64
#define INNER   1024
#define ROWS    (BATCH*NSEQ)   // 8192
#define QKVW    (3*INNER)      // 3072

// Scratch (device globals: allocation-free per harness rules)
__device__ float g_xn [ROWS*DIM];     // 32 MB
__device__ float g_qkv[ROWS*QKVW];    // 96 MB
__device__ float g_att[ROWS*INNER];   // 32 MB

// ---------------------------------------------------------------------------
// LayerNorm: one block per row, 256 threads, one float4 per thread.
// ---------------------------------------------------------------------------
__global__ __launch_bounds__(256) void ln_kernel(
    const float* __restrict__ x, const float* __restrict__ gamma,
    const float* __restrict__ beta)
{
    int row = blockIdx.x;
    int t = threadIdx.x;
    const float4 v = ((const float4*)(x + (size_t)row*DIM))[t];

    float s  = v.x + v.y + v.z + v.w;
    float ss = v.x*v.x + v.y*v.y + v.z*v.z + v.w*v.w;
    #pragma unroll
    for (int o = 16; o > 0; o >>= 1) {
        s  += __shfl_xor_sync(0xFFFFFFFFu, s,  o);
        ss += __shfl_xor_sync(0xFFFFFFFFu, ss, o);
    }
    __shared__ float rs[8], rss[8];
    int w = t >> 5, l = t & 31;
    if (l == 0) { rs[w] = s; rss[w] = ss; }
    __syncthreads();
    if (w == 0) {
        s  = (l < 8) ? rs[l]  : 0.f;
        ss = (l < 8) ? rss[l] : 0.f;
        #pragma unroll
        for (int o = 4; o > 0; o >>= 1) {
            s  += __shfl_xor_sync(0xFFFFFFFFu, s,  o);
            ss += __shfl_xor_sync(0xFFFFFFFFu, ss, o);
        }
        if (l == 0) { rs[0] = s; rss[0] = ss; }
    }
    __syncthreads();
    float mu  = rs[0]  * (1.0f/DIM);
    float var = rss[0] * (1.0f/DIM) - mu*mu;
    float inv = rsqrtf(var + 1e-5f);

    const float4 g = ((const float4*)gamma)[t];
    const float4 b = ((const float4*)beta)[t];
    float4 r;
    r.x = (v.x - mu)*inv*g.x + b.x;
    r.y = (v.y - mu)*inv*g.y + b.y;
    r.z = (v.z - mu)*inv*g.z + b.z;
    r.w = (v.w - mu)*inv*g.w + b.w;
    ((float4*)(g_xn + (size_t)row*DIM))[t] = r;
}

// ---------------------------------------------------------------------------
// SGEMM: C[M,N] = A[M,K] @ B[K,N], all row-major, dims multiples of 128/8.
// 128x128 block tile, BK=8, 8x8 per thread, 256 threads.
// ---------------------------------------------------------------------------
__global__ __launch_bounds__(256) void sgemm_kernel(
    const float* __restrict__ A, const float* __restrict__ Bm,
    float* __restrict__ C, int M, int Nn, int K)
{
    __shared__ float As[8][128];
    __shared__ float Bs[8][128];

    int tid = threadIdx.x;
    int tx = tid & 15, ty = tid >> 4;

    const float* Ab = A  + (size_t)blockIdx.y * 128 * K;
    const float* Bb = Bm + (size_t)blockIdx.x * 128;

    float acc[8][8];
    #pragma unroll
    for (int i = 0; i < 8; i++)
        #pragma unroll
        for (int j = 0; j < 8; j++) acc[i][j] = 0.f;

    int arow = tid >> 1, acol = (tid & 1) * 4;
    int brow = tid >> 5, bcol = (tid & 31) * 4;

    for (int k0 = 0; k0 < K; k0 += 8) {
        float4 a4 = *(const float4*)(Ab + (size_t)arow*K + k0 + acol);
        As[acol+0][arow] = a4.x;
        As[acol+1][arow] = a4.y;
        As[acol+2][arow] = a4.z;
        As[acol+3][arow] = a4.w;
        *(float4*)&Bs[brow][bcol] =
            *(const float4*)(Bb + (size_t)(k0 + brow)*Nn + bcol);
        __syncthreads();

        #pragma unroll
        for (int kk = 0; kk < 8; kk++) {
            float ar[8], br[8];
            #pragma unroll
            for (int i = 0; i < 8; i++) ar[i] = As[kk][ty*8 + i];
            #pragma unroll
            for (int j = 0; j < 8; j++) br[j] = Bs[kk][tx*8 + j];
            #pragma unroll
            for (int i = 0; i < 8; i++)
                #pragma unroll
                for (int j = 0; j < 8; j++)
                    acc[i][j] += ar[i] * br[j];
        }
        __syncthreads();
    }

    float* Cb = C + (size_t)(blockIdx.y*128 + ty*8)*Nn + blockIdx.x*128 + tx*8;
    #pragma unroll
    for (int i = 0; i < 8; i++) {
        *(float4*)(Cb + (size_t)i*Nn)     = make_float4(acc[i][0], acc[i][1], acc[i][2], acc[i][3]);
        *(float4*)(Cb + (size_t)i*Nn + 4) = make_float4(acc[i][4], acc[i][5], acc[i][6], acc[i][7]);
    }
}

// ---------------------------------------------------------------------------
// Flash-style biased attention.
// Grid: (b=8, qtile=16, h=16); block 256 threads.
// Per block: 64 q-rows x full 64-dim head; loops 16 kv tiles of 64.
// Thread (tr=tid/16, tc=tid%16) owns rows {4tr..4tr+3}, cols/dims {tc+16*j}.
// Smem pitch 65 -> conflict-free tc-indexed accesses.
// ---------------------------------------------------------------------------
#define SP 65
#define ATTN_SMEM (4*64*SP*sizeof(float))   // 66560 bytes

__global__ __launch_bounds__(256) void attn_kernel(const float* __restrict__ bias)
{
    extern __shared__ float sm[];
    float* qs = sm;               // [64][SP]
    float* ks = qs + 64*SP;
    float* vs = ks + 64*SP;
    float* ps = vs + 64*SP;

    const int b  = blockIdx.x;
    const int qt = blockIdx.y;
    const int h  = blockIdx.z;
    const int tid = threadIdx.x;
    const int tr = tid >> 4, tc = tid & 15;

    const float* qbase = g_qkv + (size_t)(b*NSEQ + qt*64)*QKVW + h*DHEAD;
    const float* kbase = g_qkv + (size_t)(b*NSEQ)*QKVW + INNER   + h*DHEAD;
    const float* vbase = g_qkv + (size_t)(b*NSEQ)*QKVW + 2*INNER + h*DHEAD;
    const float* bbase = bias + ((size_t)h*NSEQ + qt*64)*NSEQ;

    // load q tile (scaled by 1/sqrt(64))
    {
        int r = (tid >> 4);
        int c = (tid & 15) * 4;
        #pragma unroll
        for (int p = 0; p < 4; p++) {
            int row = p*16 + r;
            float4 v = *(const float4*)(qbase + (size_t)row*QKVW + c);
            qs[row*SP + c + 0] = v.x * 0.125f;
            qs[row*SP + c + 1] = v.y * 0.125f;
            qs[row*SP + c + 2] = v.z * 0.125f;
            qs[row*SP + c + 3] = v.w * 0.125f;
        }
    }

    float m[4], lsum[4], acc[4][4];
    #pragma unroll
    for (int i = 0; i < 4; i++) {
        m[i] = -1e30f; lsum[i] = 0.f;
        #pragma unroll
        for (int d = 0; d < 4; d++) acc[i][d] = 0.f;
    }

    for (int kt = 0; kt < 16; kt++) {
        __syncthreads();
        // load k, v tiles
        {
            int r = (tid >> 4);
            int c = (tid & 15) * 4;
            #pragma unroll
            for (int p = 0; p < 4; p++) {
                int row = p*16 + r;
                float4 kv = *(const float4*)(kbase + (size_t)(kt*64 + row)*QKVW + c);
                ks[row*SP + c + 0] = kv.x;
                ks[row*SP + c + 1] = kv.y;
                ks[row*SP + c + 2] = kv.z;
                ks[row*SP + c + 3] = kv.w;
                float4 vv = *(const float4*)(vbase + (size_t)(kt*64 + row)*QKVW + c);
                vs[row*SP + c + 0] = vv.x;
                vs[row*SP + c + 1] = vv.y;
                vs[row*SP + c + 2] = vv.z;
                vs[row*SP + c + 3] = vv.w;
            }
        }
        __syncthreads();

        // scores = bias + q.k^T
        float sc[4][4];
        #pragma unroll
        for (int ii = 0; ii < 4; ii++)
            #pragma unroll
            for (int jj = 0; jj < 4; jj++)
                sc[ii][jj] = bbase[(size_t)(tr*4 + ii)*NSEQ + kt*64 + tc + 16*jj];

        #pragma unroll 4
        for (int kk = 0; kk < 64; kk++) {
            float qv[4], kv[4];
            #pragma unroll
            for (int ii = 0; ii < 4; ii++) qv[ii] = qs[(4*tr + ii)*SP + kk];
            #pragma unroll
            for (int jj = 0; jj < 4; jj++) kv[jj] = ks[(tc + 16*jj)*SP + kk];
            #pragma unroll
            for (int ii = 0; ii < 4; ii++)
                #pragma unroll
                for (int jj = 0; jj < 4; jj++)
                    sc[ii][jj] += qv[ii] * kv[jj];
        }

        // online softmax per row (row group = 16 lanes with same tr)
        #pragma unroll
        for (int ii = 0; ii < 4; ii++) {
            float mx = fmaxf(fmaxf(sc[ii][0], sc[ii][1]), fmaxf(sc[ii][2], sc[ii][3]));
            mx = fmaxf(mx, __shfl_xor_sync(0xFFFFFFFFu, mx, 1));
            mx = fmaxf(mx, __shfl_xor_sync(0xFFFFFFFFu, mx, 2));
            mx = fmaxf(mx, __shfl_xor_sync(0xFFFFFFFFu, mx, 4));
            mx = fmaxf(mx, __shfl_xor_sync(0xFFFFFFFFu, mx, 8));
            float mnew = fmaxf(m[ii], mx);
            float corr = __expf(m[ii] - mnew);
            m[ii] = mnew;
            float p4[4], psum = 0.f;
            #pragma unroll
            for (int jj = 0; jj < 4; jj++) {
                p4[jj] = __expf(sc[ii][jj] - mnew);
                psum += p4[jj];
            }
            psum += __shfl_xor_sync(0xFFFFFFFFu, psum, 1);
            psum += __shfl_xor_sync(0xFFFFFFFFu, psum, 2);
            psum += __shfl_xor_sync(0xFFFFFFFFu, psum, 4);
            psum += __shfl_xor_sync(0xFFFFFFFFu, psum, 8);
            lsum[ii] = lsum[ii]*corr + psum;
            #pragma unroll
            for (int d = 0; d < 4; d++) acc[ii][d] *= corr;
            #pragma unroll
            for (int jj = 0; jj < 4; jj++)
                ps[(4*tr + ii)*SP + tc + 16*jj] = p4[jj];
        }
        __syncwarp();

        // out += P @ V
        #pragma unroll 4
        for (int j = 0; j < 64; j++) {
            float pv[4], vv[4];
            #pragma unroll
            for (int ii = 0; ii < 4; ii++) pv[ii] = ps[(4*tr + ii)*SP + j];
            #pragma unroll
            for (int d = 0; d < 4; d++) vv[d] = vs[j*SP + tc + 16*d];
            #pragma unroll
            for (int ii = 0; ii < 4; ii++)
                #pragma unroll
                for (int d = 0; d < 4; d++)
                    acc[ii][d] += pv[ii] * vv[d];
        }
    }

    // epilogue: normalize and write in [b,n,(h d)] layout
    #pragma unroll
    for (int ii = 0; ii < 4; ii++) {
        float invl = 1.0f / lsum[ii];
        size_t row = (size_t)(b*NSEQ + qt*64 + 4*tr + ii);
        #pragma unroll
        for (int d = 0; d < 4; d++)
            g_att[row*INNER + h*DHEAD + tc + 16*d] = acc[ii][d] * invl;
    }
}

// ---------------------------------------------------------------------------
extern "C" void kernel_launch(void* const* d_in, const int* in_sizes, int n_in,
                              void* d_out, int out_size)
{
    const float* x     = (const float*)d_in[0];
    const float* gamma = (const float*)d_in[1];
    const float* beta  = (const float*)d_in[2];
    const float* wqkv  = (const float*)d_in[3];
    const float* wout  = (const float*)d_in[4];
    const float* bias  = (const float*)d_in[5];
    float* out = (float*)d_out;

    float *xn, *qkv, *att;
    cudaGetSymbolAddress((void**)&xn,  g_xn);
    cudaGetSymbolAddress((void**)&qkv, g_qkv);
    cudaGetSymbolAddress((void**)&att, g_att);

    cudaFuncSetAttribute(attn_kernel,
                         cudaFuncAttributeMaxDynamicSharedMemorySize,
                         (int)ATTN_SMEM);

    ln_kernel<<<ROWS, 256>>>(x, gamma, beta);
    sgemm_kernel<<<dim3(QKVW/128, ROWS/128), 256>>>(xn, wqkv, qkv, ROWS, QKVW, DIM);
    attn_kernel<<<dim3(BATCH, NSEQ/64, HEADS), 256, ATTN_SMEM>>>(bias);
    sgemm_kernel<<<dim3(DIM/128, ROWS/128), 256>>>(att, wout, out, ROWS, DIM, INNER);
}

// round 2
// speedup vs baseline: 1.1002x; 1.1002x over previous
#include <cuda_runtime.h>
#include <math.h>

#define BATCH   8
#define NSEQ    1024
#define DIM     1024
#define HEADS   16
#define DHEAD   64
#define INNER   1024
#define ROWS    (BATCH*NSEQ)   // 8192
#define QKVW    (3*INNER)      // 3072

// Scratch (device globals: allocation-free per harness rules)
__device__ float g_xn  [ROWS*DIM];     // 32 MB, tf32-rounded
__device__ float g_qkv [ROWS*QKVW];    // 96 MB, fp32
__device__ float g_att [ROWS*INNER];   // 32 MB, tf32-rounded
__device__ float g_wqkv[DIM*QKVW];     // 12 MB, tf32-rounded
__device__ float g_wout[INNER*DIM];    //  4 MB, tf32-rounded

__device__ __forceinline__ unsigned f2tf32(float f) {
    unsigned u;
    asm("cvt.rna.tf32.f32 %0, %1;" : "=r"(u) : "f"(f));
    return u;
}
__device__ __forceinline__ float rnd_tf32(float f) {
    return __uint_as_float(f2tf32(f));
}

// ---------------------------------------------------------------------------
// Round an fp32 array to tf32 (rna) — used on constant weights once per call.
// ---------------------------------------------------------------------------
__global__ __launch_bounds__(256) void round_tf32_kernel(
    const float* __restrict__ in, float* __restrict__ out, int n4)
{
    int i = blockIdx.x * 256 + threadIdx.x;
    if (i < n4) {
        float4 v = ((const float4*)in)[i];
        v.x = rnd_tf32(v.x); v.y = rnd_tf32(v.y);
        v.z = rnd_tf32(v.z); v.w = rnd_tf32(v.w);
        ((float4*)out)[i] = v;
    }
}

// ---------------------------------------------------------------------------
// LayerNorm: one block per row; output rounded to tf32 (feeds tf32 GEMM).
// ---------------------------------------------------------------------------
__global__ __launch_bounds__(256) void ln_kernel(
    const float* __restrict__ x, const float* __restrict__ gamma,
    const float* __restrict__ beta)
{
    int row = blockIdx.x;
    int t = threadIdx.x;
    const float4 v = ((const float4*)(x + (size_t)row*DIM))[t];

    float s  = v.x + v.y + v.z + v.w;
    float ss = v.x*v.x + v.y*v.y + v.z*v.z + v.w*v.w;
    #pragma unroll
    for (int o = 16; o > 0; o >>= 1) {
        s  += __shfl_xor_sync(0xFFFFFFFFu, s,  o);
        ss += __shfl_xor_sync(0xFFFFFFFFu, ss, o);
    }
    __shared__ float rs[8], rss[8];
    int w = t >> 5, l = t & 31;
    if (l == 0) { rs[w] = s; rss[w] = ss; }
    __syncthreads();
    if (w == 0) {
        s  = (l < 8) ? rs[l]  : 0.f;
        ss = (l < 8) ? rss[l] : 0.f;
        #pragma unroll
        for (int o = 4; o > 0; o >>= 1) {
            s  += __shfl_xor_sync(0xFFFFFFFFu, s,  o);
            ss += __shfl_xor_sync(0xFFFFFFFFu, ss, o);
        }
        if (l == 0) { rs[0] = s; rss[0] = ss; }
    }
    __syncthreads();
    float mu  = rs[0]  * (1.0f/DIM);
    float var = rss[0] * (1.0f/DIM) - mu*mu;
    float inv = rsqrtf(var + 1e-5f);

    const float4 g = ((const float4*)gamma)[t];
    const float4 b = ((const float4*)beta)[t];
    float4 r;
    r.x = rnd_tf32((v.x - mu)*inv*g.x + b.x);
    r.y = rnd_tf32((v.y - mu)*inv*g.y + b.y);
    r.z = rnd_tf32((v.z - mu)*inv*g.z + b.z);
    r.w = rnd_tf32((v.w - mu)*inv*g.w + b.w);
    ((float4*)(g_xn + (size_t)row*DIM))[t] = r;
}

// ---------------------------------------------------------------------------
// TF32 tensor-core GEMM: C[M,N] = A[M,K] @ B[K,N], row-major fp32 storage
// (values pre-rounded to tf32). 128x128 block, BK=16, cp.async double buffer,
// 8 warps, warp tile 32x64, mma.sync.m16n8k8.
// Smem strides: As [m][k] stride 20, Bs [k][n] stride 136 -> conflict-free
// fragment loads (verified bank math).
// ---------------------------------------------------------------------------
#define ASTR 20
#define BSTR 136

__global__ __launch_bounds__(256) void gemm_tf32(
    const float* __restrict__ A, const float* __restrict__ B,
    float* __restrict__ C, int M, int N, int K)
{
    __shared__ float As[2][128*ASTR];
    __shared__ float Bs[2][16*BSTR];

    const int tid  = threadIdx.x;
    const int lane = tid & 31;
    const int warp = tid >> 5;
    const int wm = (warp & 3) * 32;
    const int wn = (warp >> 2) * 64;
    const int bm = blockIdx.y * 128;
    const int bn = blockIdx.x * 128;

    float acc[2][8][4];
    #pragma unroll
    for (int i = 0; i < 2; i++)
        #pragma unroll
        for (int j = 0; j < 8; j++)
            #pragma unroll
            for (int q = 0; q < 4; q++) acc[i][j][q] = 0.f;

    const int NK = K / 16;

    // stage-load lambda replacement (macro-ish via explicit code in loop)
    #define LOAD_STAGE(s, k0)                                                     \
    {                                                                             \
        _Pragma("unroll")                                                         \
        for (int h = 0; h < 2; h++) {                                             \
            int c = tid + h*256;                                                  \
            int row = c >> 2, kc = (c & 3) * 4;                                   \
            unsigned dst = (unsigned)__cvta_generic_to_shared(                    \
                                &As[s][row*ASTR + kc]);                           \
            const float* src = A + (size_t)(bm + row)*K + (k0) + kc;              \
            asm volatile("cp.async.ca.shared.global [%0], [%1], 16;"              \
                         :: "r"(dst), "l"(src));                                  \
        }                                                                         \
        _Pragma("unroll")                                                         \
        for (int h = 0; h < 2; h++) {                                             \
            int c = tid + h*256;                                                  \
            int row = c >> 5, col = (c & 31) * 4;                                 \
            unsigned dst = (unsigned)__cvta_generic_to_shared(                    \
                                &Bs[s][row*BSTR + col]);                          \
            const float* src = B + (size_t)((k0) + row)*N + bn + col;             \
            asm volatile("cp.async.ca.shared.global [%0], [%1], 16;"              \
                         :: "r"(dst), "l"(src));                                  \
        }                                                                         \
        asm volatile("cp.async.commit_group;");                                   \
    }

    LOAD_STAGE(0, 0)

    for (int kt = 0; kt < NK; kt++) {
        if (kt + 1 < NK) {
            LOAD_STAGE((kt+1)&1, (kt+1)*16)
            asm volatile("cp.async.wait_group 1;");
        } else {
            asm volatile("cp.async.wait_group 0;");
        }
        __syncthreads();

        const float* as = As[kt & 1];
        const float* bs = Bs[kt & 1];

        #pragma unroll
        for (int kk = 0; kk < 2; kk++) {
            const int k8 = kk * 8;
            unsigned af[2][4];
            #pragma unroll
            for (int mt = 0; mt < 2; mt++) {
                int m0 = wm + mt*16 + (lane >> 2);
                af[mt][0] = __float_as_uint(as[(m0    )*ASTR + k8     + (lane & 3)]);
                af[mt][1] = __float_as_uint(as[(m0 + 8)*ASTR + k8     + (lane & 3)]);
                af[mt][2] = __float_as_uint(as[(m0    )*ASTR + k8 + 4 + (lane & 3)]);
                af[mt][3] = __float_as_uint(as[(m0 + 8)*ASTR + k8 + 4 + (lane & 3)]);
            }
            unsigned bf[8][2];
            #pragma unroll
            for (int nt = 0; nt < 8; nt++) {
                int n0 = wn + nt*8 + (lane >> 2);
                bf[nt][0] = __float_as_uint(bs[(k8     + (lane & 3))*BSTR + n0]);
                bf[nt][1] = __float_as_uint(bs[(k8 + 4 + (lane & 3))*BSTR + n0]);
            }
            #pragma unroll
            for (int mt = 0; mt < 2; mt++)
                #pragma unroll
                for (int nt = 0; nt < 8; nt++) {
                    asm volatile(
                        "mma.sync.aligned.m16n8k8.row.col.f32.tf32.tf32.f32 "
                        "{%0,%1,%2,%3},{%4,%5,%6,%7},{%8,%9},{%0,%1,%2,%3};"
                        : "+f"(acc[mt][nt][0]), "+f"(acc[mt][nt][1]),
                          "+f"(acc[mt][nt][2]), "+f"(acc[mt][nt][3])
                        : "r"(af[mt][0]), "r"(af[mt][1]),
                          "r"(af[mt][2]), "r"(af[mt][3]),
                          "r"(bf[nt][0]), "r"(bf[nt][1]));
                }
        }
        __syncthreads();
    }

    // epilogue
    #pragma unroll
    for (int mt = 0; mt < 2; mt++) {
        int r0 = bm + wm + mt*16 + (lane >> 2);
        #pragma unroll
        for (int nt = 0; nt < 8; nt++) {
            int cc = bn + wn + nt*8 + (lane & 3)*2;
            *(float2*)&C[(size_t)r0*N + cc] =
                make_float2(acc[mt][nt][0], acc[mt][nt][1]);
            *(float2*)&C[(size_t)(r0+8)*N + cc] =
                make_float2(acc[mt][nt][2], acc[mt][nt][3]);
        }
    }
}

// ---------------------------------------------------------------------------
// Flash-style biased attention (fp32 SIMT) — unchanged except tf32-rounded
// epilogue output (feeds tf32 out-projection GEMM).
// ---------------------------------------------------------------------------
#define SP 65
#define ATTN_SMEM (4*64*SP*sizeof(float))   // 66560 bytes

__global__ __launch_bounds__(256) void attn_kernel(const float* __restrict__ bias)
{
    extern __shared__ float sm[];
    float* qs = sm;               // [64][SP]
    float* ks = qs + 64*SP;
    float* vs = ks + 64*SP;
    float* ps = vs + 64*SP;

    const int b  = blockIdx.x;
    const int qt = blockIdx.y;
    const int h  = blockIdx.z;
    const int tid = threadIdx.x;
    const int tr = tid >> 4, tc = tid & 15;

    const float* qbase = g_qkv + (size_t)(b*NSEQ + qt*64)*QKVW + h*DHEAD;
    const float* kbase = g_qkv + (size_t)(b*NSEQ)*QKVW + INNER   + h*DHEAD;
    const float* vbase = g_qkv + (size_t)(b*NSEQ)*QKVW + 2*INNER + h*DHEAD;
    const float* bbase = bias + ((size_t)h*NSEQ + qt*64)*NSEQ;

    {
        int r = (tid >> 4);
        int c = (tid & 15) * 4;
        #pragma unroll
        for (int p = 0; p < 4; p++) {
            int row = p*16 + r;
            float4 v = *(const float4*)(qbase + (size_t)row*QKVW + c);
            qs[row*SP + c + 0] = v.x * 0.125f;
            qs[row*SP + c + 1] = v.y * 0.125f;
            qs[row*SP + c + 2] = v.z * 0.125f;
            qs[row*SP + c + 3] = v.w * 0.125f;
        }
    }

    float m[4], lsum[4], acc[4][4];
    #pragma unroll
    for (int i = 0; i < 4; i++) {
        m[i] = -1e30f; lsum[i] = 0.f;
        #pragma unroll
        for (int d = 0; d < 4; d++) acc[i][d] = 0.f;
    }

    for (int kt = 0; kt < 16; kt++) {
        __syncthreads();
        {
            int r = (tid >> 4);
            int c = (tid & 15) * 4;
            #pragma unroll
            for (int p = 0; p < 4; p++) {
                int row = p*16 + r;
                float4 kv = *(const float4*)(kbase + (size_t)(kt*64 + row)*QKVW + c);
                ks[row*SP + c + 0] = kv.x;
                ks[row*SP + c + 1] = kv.y;
                ks[row*SP + c + 2] = kv.z;
                ks[row*SP + c + 3] = kv.w;
                float4 vv = *(const float4*)(vbase + (size_t)(kt*64 + row)*QKVW + c);
                vs[row*SP + c + 0] = vv.x;
                vs[row*SP + c + 1] = vv.y;
                vs[row*SP + c + 2] = vv.z;
                vs[row*SP + c + 3] = vv.w;
            }
        }
        __syncthreads();

        float sc[4][4];
        #pragma unroll
        for (int ii = 0; ii < 4; ii++)
            #pragma unroll
            for (int jj = 0; jj < 4; jj++)
                sc[ii][jj] = bbase[(size_t)(tr*4 + ii)*NSEQ + kt*64 + tc + 16*jj];

        #pragma unroll 4
        for (int kk = 0; kk < 64; kk++) {
            float qv[4], kv[4];
            #pragma unroll
            for (int ii = 0; ii < 4; ii++) qv[ii] = qs[(4*tr + ii)*SP + kk];
            #pragma unroll
            for (int jj = 0; jj < 4; jj++) kv[jj] = ks[(tc + 16*jj)*SP + kk];
            #pragma unroll
            for (int ii = 0; ii < 4; ii++)
                #pragma unroll
                for (int jj = 0; jj < 4; jj++)
                    sc[ii][jj] += qv[ii] * kv[jj];
        }

        #pragma unroll
        for (int ii = 0; ii < 4; ii++) {
            float mx = fmaxf(fmaxf(sc[ii][0], sc[ii][1]), fmaxf(sc[ii][2], sc[ii][3]));
            mx = fmaxf(mx, __shfl_xor_sync(0xFFFFFFFFu, mx, 1));
            mx = fmaxf(mx, __shfl_xor_sync(0xFFFFFFFFu, mx, 2));
            mx = fmaxf(mx, __shfl_xor_sync(0xFFFFFFFFu, mx, 4));
            mx = fmaxf(mx, __shfl_xor_sync(0xFFFFFFFFu, mx, 8));
            float mnew = fmaxf(m[ii], mx);
            float corr = __expf(m[ii] - mnew);
            m[ii] = mnew;
            float p4[4], psum = 0.f;
            #pragma unroll
            for (int jj = 0; jj < 4; jj++) {
                p4[jj] = __expf(sc[ii][jj] - mnew);
                psum += p4[jj];
            }
            psum += __shfl_xor_sync(0xFFFFFFFFu, psum, 1);
            psum += __shfl_xor_sync(0xFFFFFFFFu, psum, 2);
            psum += __shfl_xor_sync(0xFFFFFFFFu, psum, 4);
            psum += __shfl_xor_sync(0xFFFFFFFFu, psum, 8);
            lsum[ii] = lsum[ii]*corr + psum;
            #pragma unroll
            for (int d = 0; d < 4; d++) acc[ii][d] *= corr;
            #pragma unroll
            for (int jj = 0; jj < 4; jj++)
                ps[(4*tr + ii)*SP + tc + 16*jj] = p4[jj];
        }
        __syncwarp();

        #pragma unroll 4
        for (int j = 0; j < 64; j++) {
            float pv[4], vv[4];
            #pragma unroll
            for (int ii = 0; ii < 4; ii++) pv[ii] = ps[(4*tr + ii)*SP + j];
            #pragma unroll
            for (int d = 0; d < 4; d++) vv[d] = vs[j*SP + tc + 16*d];
            #pragma unroll
            for (int ii = 0; ii < 4; ii++)
                #pragma unroll
                for (int d = 0; d < 4; d++)
                    acc[ii][d] += pv[ii] * vv[d];
        }
    }

    #pragma unroll
    for (int ii = 0; ii < 4; ii++) {
        float invl = 1.0f / lsum[ii];
        size_t row = (size_t)(b*NSEQ + qt*64 + 4*tr + ii);
        #pragma unroll
        for (int d = 0; d < 4; d++)
            g_att[row*INNER + h*DHEAD + tc + 16*d] = rnd_tf32(acc[ii][d] * invl);
    }
}

// ---------------------------------------------------------------------------
extern "C" void kernel_launch(void* const* d_in, const int* in_sizes, int n_in,
                              void* d_out, int out_size)
{
    const float* x     = (const float*)d_in[0];
    const float* gamma = (const float*)d_in[1];
    const float* beta  = (const float*)d_in[2];
    const float* wqkv  = (const float*)d_in[3];
    const float* wout  = (const float*)d_in[4];
    const float* bias  = (const float*)d_in[5];
    float* out = (float*)d_out;

    float *xn, *qkv, *att, *wqkv_t, *wout_t;
    cudaGetSymbolAddress((void**)&xn,     g_xn);
    cudaGetSymbolAddress((void**)&qkv,    g_qkv);
    cudaGetSymbolAddress((void**)&att,    g_att);
    cudaGetSymbolAddress((void**)&wqkv_t, g_wqkv);
    cudaGetSymbolAddress((void**)&wout_t, g_wout);

    cudaFuncSetAttribute(attn_kernel,
                         cudaFuncAttributeMaxDynamicSharedMemorySize,
                         (int)ATTN_SMEM);

    round_tf32_kernel<<<(DIM*QKVW/4 + 255)/256, 256>>>(wqkv, wqkv_t, DIM*QKVW/4);
    round_tf32_kernel<<<(INNER*DIM/4 + 255)/256, 256>>>(wout, wout_t, INNER*DIM/4);
    ln_kernel<<<ROWS, 256>>>(x, gamma, beta);
    gemm_tf32<<<dim3(QKVW/128, ROWS/128), 256>>>(xn, wqkv_t, qkv, ROWS, QKVW, DIM);
    attn_kernel<<<dim3(BATCH, NSEQ/64, HEADS), 256, ATTN_SMEM>>>(bias);
    gemm_tf32<<<dim3(DIM/128, ROWS/128), 256>>>(att, wout_t, out, ROWS, DIM, INNER);
}

// round 3
// speedup vs baseline: 2.9778x; 2.7067x over previous
#include <cuda_runtime.h>
#include <math.h>

#define BATCH   8
#define NSEQ    1024
#define DIM     1024
#define HEADS   16
#define DHEAD   64
#define INNER   1024
#define ROWS    (BATCH*NSEQ)   // 8192
#define QKVW    (3*INNER)      // 3072

// Scratch (device globals: allocation-free per harness rules)
__device__ float g_xn  [ROWS*DIM];     // 32 MB, tf32-rounded
__device__ float g_qkv [ROWS*QKVW];    // 96 MB, fp32
__device__ float g_att [ROWS*INNER];   // 32 MB, tf32-rounded
__device__ float g_wqkv[DIM*QKVW];     // 12 MB, tf32-rounded
__device__ float g_wout[INNER*DIM];    //  4 MB, tf32-rounded

__device__ __forceinline__ unsigned f2tf32(float f) {
    unsigned u;
    asm("cvt.rna.tf32.f32 %0, %1;" : "=r"(u) : "f"(f));
    return u;
}
__device__ __forceinline__ float rnd_tf32(float f) {
    return __uint_as_float(f2tf32(f));
}

// ---------------------------------------------------------------------------
// Round an fp32 array to tf32 (rna) — for constant weights.
// ---------------------------------------------------------------------------
__global__ __launch_bounds__(256) void round_tf32_kernel(
    const float* __restrict__ in, float* __restrict__ out, int n4)
{
    int i = blockIdx.x * 256 + threadIdx.x;
    if (i < n4) {
        float4 v = ((const float4*)in)[i];
        v.x = rnd_tf32(v.x); v.y = rnd_tf32(v.y);
        v.z = rnd_tf32(v.z); v.w = rnd_tf32(v.w);
        ((float4*)out)[i] = v;
    }
}

// ---------------------------------------------------------------------------
// LayerNorm: one block per row; output rounded to tf32 (feeds tf32 GEMM).
// ---------------------------------------------------------------------------
__global__ __launch_bounds__(256) void ln_kernel(
    const float* __restrict__ x, const float* __restrict__ gamma,
    const float* __restrict__ beta)
{
    int row = blockIdx.x;
    int t = threadIdx.x;
    const float4 v = ((const float4*)(x + (size_t)row*DIM))[t];

    float s  = v.x + v.y + v.z + v.w;
    float ss = v.x*v.x + v.y*v.y + v.z*v.z + v.w*v.w;
    #pragma unroll
    for (int o = 16; o > 0; o >>= 1) {
        s  += __shfl_xor_sync(0xFFFFFFFFu, s,  o);
        ss += __shfl_xor_sync(0xFFFFFFFFu, ss, o);
    }
    __shared__ float rs[8], rss[8];
    int w = t >> 5, l = t & 31;
    if (l == 0) { rs[w] = s; rss[w] = ss; }
    __syncthreads();
    if (w == 0) {
        s  = (l < 8) ? rs[l]  : 0.f;
        ss = (l < 8) ? rss[l] : 0.f;
        #pragma unroll
        for (int o = 4; o > 0; o >>= 1) {
            s  += __shfl_xor_sync(0xFFFFFFFFu, s,  o);
            ss += __shfl_xor_sync(0xFFFFFFFFu, ss, o);
        }
        if (l == 0) { rs[0] = s; rss[0] = ss; }
    }
    __syncthreads();
    float mu  = rs[0]  * (1.0f/DIM);
    float var = rss[0] * (1.0f/DIM) - mu*mu;
    float inv = rsqrtf(var + 1e-5f);

    const float4 g = ((const float4*)gamma)[t];
    const float4 b = ((const float4*)beta)[t];
    float4 r;
    r.x = rnd_tf32((v.x - mu)*inv*g.x + b.x);
    r.y = rnd_tf32((v.y - mu)*inv*g.y + b.y);
    r.z = rnd_tf32((v.z - mu)*inv*g.z + b.z);
    r.w = rnd_tf32((v.w - mu)*inv*g.w + b.w);
    ((float4*)(g_xn + (size_t)row*DIM))[t] = r;
}

// ---------------------------------------------------------------------------
// TF32 tensor-core GEMM (unchanged from round 2).
// ---------------------------------------------------------------------------
#define ASTR 20
#define BSTR 136

__global__ __launch_bounds__(256) void gemm_tf32(
    const float* __restrict__ A, const float* __restrict__ B,
    float* __restrict__ C, int M, int N, int K)
{
    __shared__ float As[2][128*ASTR];
    __shared__ float Bs[2][16*BSTR];

    const int tid  = threadIdx.x;
    const int lane = tid & 31;
    const int warp = tid >> 5;
    const int wm = (warp & 3) * 32;
    const int wn = (warp >> 2) * 64;
    const int bm = blockIdx.y * 128;
    const int bn = blockIdx.x * 128;

    float acc[2][8][4];
    #pragma unroll
    for (int i = 0; i < 2; i++)
        #pragma unroll
        for (int j = 0; j < 8; j++)
            #pragma unroll
            for (int q = 0; q < 4; q++) acc[i][j][q] = 0.f;

    const int NK = K / 16;

    #define LOAD_STAGE(s, k0)                                                     \
    {                                                                             \
        _Pragma("unroll")                                                         \
        for (int h = 0; h < 2; h++) {                                             \
            int c = tid + h*256;                                                  \
            int row = c >> 2, kc = (c & 3) * 4;                                   \
            unsigned dst = (unsigned)__cvta_generic_to_shared(                    \
                                &As[s][row*ASTR + kc]);                           \
            const float* src = A + (size_t)(bm + row)*K + (k0) + kc;              \
            asm volatile("cp.async.ca.shared.global [%0], [%1], 16;"              \
                         :: "r"(dst), "l"(src));                                  \
        }                                                                         \
        _Pragma("unroll")                                                         \
        for (int h = 0; h < 2; h++) {                                             \
            int c = tid + h*256;                                                  \
            int row = c >> 5, col = (c & 31) * 4;                                 \
            unsigned dst = (unsigned)__cvta_generic_to_shared(                    \
                                &Bs[s][row*BSTR + col]);                          \
            const float* src = B + (size_t)((k0) + row)*N + bn + col;             \
            asm volatile("cp.async.ca.shared.global [%0], [%1], 16;"              \
                         :: "r"(dst), "l"(src));                                  \
        }                                                                         \
        asm volatile("cp.async.commit_group;");                                   \
    }

    LOAD_STAGE(0, 0)

    for (int kt = 0; kt < NK; kt++) {
        if (kt + 1 < NK) {
            LOAD_STAGE((kt+1)&1, (kt+1)*16)
            asm volatile("cp.async.wait_group 1;");
        } else {
            asm volatile("cp.async.wait_group 0;");
        }
        __syncthreads();

        const float* as = As[kt & 1];
        const float* bs = Bs[kt & 1];

        #pragma unroll
        for (int kk = 0; kk < 2; kk++) {
            const int k8 = kk * 8;
            unsigned af[2][4];
            #pragma unroll
            for (int mt = 0; mt < 2; mt++) {
                int m0 = wm + mt*16 + (lane >> 2);
                af[mt][0] = __float_as_uint(as[(m0    )*ASTR + k8     + (lane & 3)]);
                af[mt][1] = __float_as_uint(as[(m0 + 8)*ASTR + k8     + (lane & 3)]);
                af[mt][2] = __float_as_uint(as[(m0    )*ASTR + k8 + 4 + (lane & 3)]);
                af[mt][3] = __float_as_uint(as[(m0 + 8)*ASTR + k8 + 4 + (lane & 3)]);
            }
            unsigned bf[8][2];
            #pragma unroll
            for (int nt = 0; nt < 8; nt++) {
                int n0 = wn + nt*8 + (lane >> 2);
                bf[nt][0] = __float_as_uint(bs[(k8     + (lane & 3))*BSTR + n0]);
                bf[nt][1] = __float_as_uint(bs[(k8 + 4 + (lane & 3))*BSTR + n0]);
            }
            #pragma unroll
            for (int mt = 0; mt < 2; mt++)
                #pragma unroll
                for (int nt = 0; nt < 8; nt++) {
                    asm volatile(
                        "mma.sync.aligned.m16n8k8.row.col.f32.tf32.tf32.f32 "
                        "{%0,%1,%2,%3},{%4,%5,%6,%7},{%8,%9},{%0,%1,%2,%3};"
                        : "+f"(acc[mt][nt][0]), "+f"(acc[mt][nt][1]),
                          "+f"(acc[mt][nt][2]), "+f"(acc[mt][nt][3])
                        : "r"(af[mt][0]), "r"(af[mt][1]),
                          "r"(af[mt][2]), "r"(af[mt][3]),
                          "r"(bf[nt][0]), "r"(bf[nt][1]));
                }
        }
        __syncthreads();
    }

    #pragma unroll
    for (int mt = 0; mt < 2; mt++) {
        int r0 = bm + wm + mt*16 + (lane >> 2);
        #pragma unroll
        for (int nt = 0; nt < 8; nt++) {
            int cc = bn + wn + nt*8 + (lane & 3)*2;
            *(float2*)&C[(size_t)r0*N + cc] =
                make_float2(acc[mt][nt][0], acc[mt][nt][1]);
            *(float2*)&C[(size_t)(r0+8)*N + cc] =
                make_float2(acc[mt][nt][2], acc[mt][nt][3]);
        }
    }
}

// ---------------------------------------------------------------------------
// Tensor-core flash attention (tf32 mma.sync).
// Grid (b=8, qt=8, h=16); 128 threads = 4 warps.
// Block: 128 q-rows x dhead 64; kv tiles of 64. Warp tile 32 q-rows.
// S accum initialized with bias (free bias add). Online softmax in accum
// layout; P staged through per-warp smem (pitch 68 -> bank==lane).
// V smem pitch 72 (==8 mod 32) -> conflict-free B-fragment reads.
// ---------------------------------------------------------------------------
#define ATP  68
#define ATPV 72
#define ATTN_SMEM ((128*ATP + 64*ATP + 64*ATPV + 4*32*ATP)*sizeof(float)) // 105472

__global__ __launch_bounds__(128) void attn_tc_kernel(const float* __restrict__ bias)
{
    extern __shared__ float sm[];
    float* Qs = sm;                         // [128][ATP]
    float* Ks = Qs + 128*ATP;               // [64][ATP]
    float* Vs = Ks + 64*ATP;                // [64][ATPV]
    float* PsAll = Vs + 64*ATPV;            // [4][32][ATP]

    const int b  = blockIdx.x;
    const int qt = blockIdx.y;
    const int h  = blockIdx.z;
    const int tid  = threadIdx.x;
    const int lane = tid & 31;
    const int warp = tid >> 5;
    const int wq = warp * 32;               // warp's q-row offset in block
    float* Ps = PsAll + warp*32*ATP;

    const int lr = lane >> 2;               // fragment row lane
    const int lc = lane & 3;                // fragment col lane

    const float* qbase = g_qkv + (size_t)(b*NSEQ + qt*128)*QKVW + h*DHEAD;
    const float* kbase = g_qkv + (size_t)(b*NSEQ)*QKVW + INNER   + h*DHEAD;
    const float* vbase = g_qkv + (size_t)(b*NSEQ)*QKVW + 2*INNER + h*DHEAD;
    const float* bb0   = bias + ((size_t)h*NSEQ + qt*128 + wq)*NSEQ;

    // load Q tile (scaled, tf32-rounded)
    #pragma unroll
    for (int p = 0; p < 16; p++) {
        int c = p*128 + tid;
        int row = c >> 4, col = (c & 15) * 4;
        float4 v = *(const float4*)(qbase + (size_t)row*QKVW + col);
        v.x = rnd_tf32(v.x * 0.125f); v.y = rnd_tf32(v.y * 0.125f);
        v.z = rnd_tf32(v.z * 0.125f); v.w = rnd_tf32(v.w * 0.125f);
        *(float4*)&Qs[row*ATP + col] = v;
    }

    float m[4], l[4];
    float co[2][8][4];
    #pragma unroll
    for (int i = 0; i < 4; i++) { m[i] = -1e30f; l[i] = 0.f; }
    #pragma unroll
    for (int mt = 0; mt < 2; mt++)
        #pragma unroll
        for (int nt = 0; nt < 8; nt++)
            #pragma unroll
            for (int q = 0; q < 4; q++) co[mt][nt][q] = 0.f;

    for (int kt = 0; kt < 16; kt++) {
        __syncthreads();
        // load K,V tiles (tf32-rounded)
        #pragma unroll
        for (int p = 0; p < 8; p++) {
            int c = p*128 + tid;
            int row = c >> 4, col = (c & 15) * 4;
            float4 kv = *(const float4*)(kbase + (size_t)(kt*64 + row)*QKVW + col);
            kv.x = rnd_tf32(kv.x); kv.y = rnd_tf32(kv.y);
            kv.z = rnd_tf32(kv.z); kv.w = rnd_tf32(kv.w);
            *(float4*)&Ks[row*ATP + col] = kv;
            float4 vv = *(const float4*)(vbase + (size_t)(kt*64 + row)*QKVW + col);
            vv.x = rnd_tf32(vv.x); vv.y = rnd_tf32(vv.y);
            vv.z = rnd_tf32(vv.z); vv.w = rnd_tf32(vv.w);
            *(float4*)&Vs[row*ATPV + col] = vv;
        }
        __syncthreads();

        // S accum initialized with bias
        float cs[2][8][4];
        const float* bb = bb0 + kt*64;
        #pragma unroll
        for (int mt = 0; mt < 2; mt++)
            #pragma unroll
            for (int hh = 0; hh < 2; hh++) {
                int roff = mt*16 + lr + 8*hh;
                #pragma unroll
                for (int nt = 0; nt < 8; nt++) {
                    float2 t = *(const float2*)(bb + (size_t)roff*NSEQ + nt*8 + 2*lc);
                    cs[mt][nt][2*hh]   = t.x;
                    cs[mt][nt][2*hh+1] = t.y;
                }
            }

        // S = Q K^T + bias
        #pragma unroll
        for (int k8 = 0; k8 < 64; k8 += 8) {
            unsigned af[2][4];
            #pragma unroll
            for (int mt = 0; mt < 2; mt++) {
                int r0 = wq + mt*16 + lr;
                af[mt][0] = __float_as_uint(Qs[(r0    )*ATP + k8     + lc]);
                af[mt][1] = __float_as_uint(Qs[(r0 + 8)*ATP + k8     + lc]);
                af[mt][2] = __float_as_uint(Qs[(r0    )*ATP + k8 + 4 + lc]);
                af[mt][3] = __float_as_uint(Qs[(r0 + 8)*ATP + k8 + 4 + lc]);
            }
            unsigned bf[8][2];
            #pragma unroll
            for (int nt = 0; nt < 8; nt++) {
                int n0 = nt*8 + lr;
                bf[nt][0] = __float_as_uint(Ks[n0*ATP + k8     + lc]);
                bf[nt][1] = __float_as_uint(Ks[n0*ATP + k8 + 4 + lc]);
            }
            #pragma unroll
            for (int mt = 0; mt < 2; mt++)
                #pragma unroll
                for (int nt = 0; nt < 8; nt++) {
                    asm volatile(
                        "mma.sync.aligned.m16n8k8.row.col.f32.tf32.tf32.f32 "
                        "{%0,%1,%2,%3},{%4,%5,%6,%7},{%8,%9},{%0,%1,%2,%3};"
                        : "+f"(cs[mt][nt][0]), "+f"(cs[mt][nt][1]),
                          "+f"(cs[mt][nt][2]), "+f"(cs[mt][nt][3])
                        : "r"(af[mt][0]), "r"(af[mt][1]),
                          "r"(af[mt][2]), "r"(af[mt][3]),
                          "r"(bf[nt][0]), "r"(bf[nt][1]));
                }
        }

        // online softmax per row; P -> smem (tf32-rounded)
        #pragma unroll
        for (int mt = 0; mt < 2; mt++)
            #pragma unroll
            for (int hh = 0; hh < 2; hh++) {
                int idx = mt*2 + hh;
                float mx = -1e30f;
                #pragma unroll
                for (int nt = 0; nt < 8; nt++)
                    mx = fmaxf(mx, fmaxf(cs[mt][nt][2*hh], cs[mt][nt][2*hh+1]));
                mx = fmaxf(mx, __shfl_xor_sync(0xFFFFFFFFu, mx, 1));
                mx = fmaxf(mx, __shfl_xor_sync(0xFFFFFFFFu, mx, 2));
                float mnew = fmaxf(m[idx], mx);
                float corr = __expf(m[idx] - mnew);
                m[idx] = mnew;
                float ls = 0.f;
                int prow = (mt*16 + lr + 8*hh)*ATP + 2*lc;
                #pragma unroll
                for (int nt = 0; nt < 8; nt++) {
                    float p0 = __expf(cs[mt][nt][2*hh]   - mnew);
                    float p1 = __expf(cs[mt][nt][2*hh+1] - mnew);
                    ls += p0 + p1;
                    Ps[prow + nt*8]     = rnd_tf32(p0);
                    Ps[prow + nt*8 + 1] = rnd_tf32(p1);
                }
                ls += __shfl_xor_sync(0xFFFFFFFFu, ls, 1);
                ls += __shfl_xor_sync(0xFFFFFFFFu, ls, 2);
                l[idx] = l[idx]*corr + ls;
                #pragma unroll
                for (int nt = 0; nt < 8; nt++) {
                    co[mt][nt][2*hh]   *= corr;
                    co[mt][nt][2*hh+1] *= corr;
                }
            }
        __syncwarp();

        // O += P V
        #pragma unroll
        for (int k8 = 0; k8 < 64; k8 += 8) {
            unsigned af[2][4];
            #pragma unroll
            for (int mt = 0; mt < 2; mt++) {
                int r0 = mt*16 + lr;
                af[mt][0] = __float_as_uint(Ps[(r0    )*ATP + k8     + lc]);
                af[mt][1] = __float_as_uint(Ps[(r0 + 8)*ATP + k8     + lc]);
                af[mt][2] = __float_as_uint(Ps[(r0    )*ATP + k8 + 4 + lc]);
                af[mt][3] = __float_as_uint(Ps[(r0 + 8)*ATP + k8 + 4 + lc]);
            }
            unsigned bf[8][2];
            #pragma unroll
            for (int nt = 0; nt < 8; nt++) {
                int n0 = nt*8 + lr;
                bf[nt][0] = __float_as_uint(Vs[(k8     + lc)*ATPV + n0]);
                bf[nt][1] = __float_as_uint(Vs[(k8 + 4 + lc)*ATPV + n0]);
            }
            #pragma unroll
            for (int mt = 0; mt < 2; mt++)
                #pragma unroll
                for (int nt = 0; nt < 8; nt++) {
                    asm volatile(
                        "mma.sync.aligned.m16n8k8.row.col.f32.tf32.tf32.f32 "
                        "{%0,%1,%2,%3},{%4,%5,%6,%7},{%8,%9},{%0,%1,%2,%3};"
                        : "+f"(co[mt][nt][0]), "+f"(co[mt][nt][1]),
                          "+f"(co[mt][nt][2]), "+f"(co[mt][nt][3])
                        : "r"(af[mt][0]), "r"(af[mt][1]),
                          "r"(af[mt][2]), "r"(af[mt][3]),
                          "r"(bf[nt][0]), "r"(bf[nt][1]));
                }
        }
    }

    // epilogue: normalize, round to tf32, write [b,n,(h d)]
    #pragma unroll
    for (int mt = 0; mt < 2; mt++)
        #pragma unroll
        for (int hh = 0; hh < 2; hh++) {
            int idx = mt*2 + hh;
            float inv = 1.0f / l[idx];
            size_t grow = (size_t)(b*NSEQ + qt*128 + wq + mt*16 + lr + 8*hh);
            #pragma unroll
            for (int nt = 0; nt < 8; nt++) {
                float2 o;
                o.x = rnd_tf32(co[mt][nt][2*hh]   * inv);
                o.y = rnd_tf32(co[mt][nt][2*hh+1] * inv);
                *(float2*)&g_att[grow*INNER + h*DHEAD + nt*8 + 2*lc] = o;
            }
        }
}

// ---------------------------------------------------------------------------
extern "C" void kernel_launch(void* const* d_in, const int* in_sizes, int n_in,
                              void* d_out, int out_size)
{
    const float* x     = (const float*)d_in[0];
    const float* gamma = (const float*)d_in[1];
    const float* beta  = (const float*)d_in[2];
    const float* wqkv  = (const float*)d_in[3];
    const float* wout  = (const float*)d_in[4];
    const float* bias  = (const float*)d_in[5];
    float* out = (float*)d_out;

    float *xn, *qkv, *att, *wqkv_t, *wout_t;
    cudaGetSymbolAddress((void**)&xn,     g_xn);
    cudaGetSymbolAddress((void**)&qkv,    g_qkv);
    cudaGetSymbolAddress((void**)&att,    g_att);
    cudaGetSymbolAddress((void**)&wqkv_t, g_wqkv);
    cudaGetSymbolAddress((void**)&wout_t, g_wout);

    cudaFuncSetAttribute(attn_tc_kernel,
                         cudaFuncAttributeMaxDynamicSharedMemorySize,
                         (int)ATTN_SMEM);

    round_tf32_kernel<<<(DIM*QKVW/4 + 255)/256, 256>>>(wqkv, wqkv_t, DIM*QKVW/4);
    round_tf32_kernel<<<(INNER*DIM/4 + 255)/256, 256>>>(wout, wout_t, INNER*DIM/4);
    ln_kernel<<<ROWS, 256>>>(x, gamma, beta);
    gemm_tf32<<<dim3(QKVW/128, ROWS/128), 256>>>(xn, wqkv_t, qkv, ROWS, QKVW, DIM);
    attn_tc_kernel<<<dim3(BATCH, NSEQ/128, HEADS), 128, ATTN_SMEM>>>(bias);
    gemm_tf32<<<dim3(DIM/128, ROWS/128), 256>>>(att, wout_t, out, ROWS, DIM, INNER);
}

// round 4
// speedup vs baseline: 3.6363x; 1.2211x over previous
#include <cuda_runtime.h>
#include <math.h>

#define BATCH   8
#define NSEQ    1024
#define DIM     1024
#define HEADS   16
#define DHEAD   64
#define INNER   1024
#define ROWS    (BATCH*NSEQ)   // 8192
#define QKVW    (3*INNER)      // 3072

// Scratch (device globals: allocation-free per harness rules)
__device__ float g_xn  [ROWS*DIM];     // tf32-rounded
__device__ float g_qkv [ROWS*QKVW];    // tf32-rounded (gemm epilogue rounds)
__device__ float g_att [ROWS*INNER];   // tf32-rounded
__device__ float g_wqkv[DIM*QKVW];     // tf32-rounded
__device__ float g_wout[INNER*DIM];    // tf32-rounded

__device__ __forceinline__ unsigned f2tf32(float f) {
    unsigned u;
    asm("cvt.rna.tf32.f32 %0, %1;" : "=r"(u) : "f"(f));
    return u;
}
__device__ __forceinline__ float rnd_tf32(float f) {
    return __uint_as_float(f2tf32(f));
}

// ---------------------------------------------------------------------------
// Round an fp32 array to tf32 (rna) — for constant weights.
// ---------------------------------------------------------------------------
__global__ __launch_bounds__(256) void round_tf32_kernel(
    const float* __restrict__ in, float* __restrict__ out, int n4)
{
    int i = blockIdx.x * 256 + threadIdx.x;
    if (i < n4) {
        float4 v = ((const float4*)in)[i];
        v.x = rnd_tf32(v.x); v.y = rnd_tf32(v.y);
        v.z = rnd_tf32(v.z); v.w = rnd_tf32(v.w);
        ((float4*)out)[i] = v;
    }
}

// ---------------------------------------------------------------------------
// LayerNorm: one block per row; output rounded to tf32 (feeds tf32 GEMM).
// ---------------------------------------------------------------------------
__global__ __launch_bounds__(256) void ln_kernel(
    const float* __restrict__ x, const float* __restrict__ gamma,
    const float* __restrict__ beta)
{
    int row = blockIdx.x;
    int t = threadIdx.x;
    const float4 v = ((const float4*)(x + (size_t)row*DIM))[t];

    float s  = v.x + v.y + v.z + v.w;
    float ss = v.x*v.x + v.y*v.y + v.z*v.z + v.w*v.w;
    #pragma unroll
    for (int o = 16; o > 0; o >>= 1) {
        s  += __shfl_xor_sync(0xFFFFFFFFu, s,  o);
        ss += __shfl_xor_sync(0xFFFFFFFFu, ss, o);
    }
    __shared__ float rs[8], rss[8];
    int w = t >> 5, l = t & 31;
    if (l == 0) { rs[w] = s; rss[w] = ss; }
    __syncthreads();
    if (w == 0) {
        s  = (l < 8) ? rs[l]  : 0.f;
        ss = (l < 8) ? rss[l] : 0.f;
        #pragma unroll
        for (int o = 4; o > 0; o >>= 1) {
            s  += __shfl_xor_sync(0xFFFFFFFFu, s,  o);
            ss += __shfl_xor_sync(0xFFFFFFFFu, ss, o);
        }
        if (l == 0) { rs[0] = s; rss[0] = ss; }
    }
    __syncthreads();
    float mu  = rs[0]  * (1.0f/DIM);
    float var = rss[0] * (1.0f/DIM) - mu*mu;
    float inv = rsqrtf(var + 1e-5f);

    const float4 g = ((const float4*)gamma)[t];
    const float4 b = ((const float4*)beta)[t];
    float4 r;
    r.x = rnd_tf32((v.x - mu)*inv*g.x + b.x);
    r.y = rnd_tf32((v.y - mu)*inv*g.y + b.y);
    r.z = rnd_tf32((v.z - mu)*inv*g.z + b.z);
    r.w = rnd_tf32((v.w - mu)*inv*g.w + b.w);
    ((float4*)(g_xn + (size_t)row*DIM))[t] = r;
}

// ---------------------------------------------------------------------------
// TF32 GEMM v2: 128x128x16 block, 4 warps, warp tile 64x64 (LDS/mma = 1.0),
// 3-stage cp.async pipeline. Optional tf32-rounded output.
// As [m][k] stride 20, Bs [k][n] stride 136 -> conflict-free fragment loads.
// ---------------------------------------------------------------------------
#define ASTR 20
#define BSTR 136
#define GSS (128*ASTR)   // A stage floats
#define GSB (16*BSTR)    // B stage floats
#define GEMM_SMEM (3*(GSS+GSB)*sizeof(float))  // 56832 B

__global__ __launch_bounds__(128) void gemm_tf32(
    const float* __restrict__ A, const float* __restrict__ B,
    float* __restrict__ C, int M, int N, int K, int roundOut)
{
    extern __shared__ float gsm[];
    float* As = gsm;
    float* Bs = gsm + 3*GSS;

    const int tid  = threadIdx.x;
    const int lane = tid & 31;
    const int warp = tid >> 5;
    const int lr = lane >> 2, lc = lane & 3;
    const int wm = (warp & 1) * 64;
    const int wn = (warp >> 1) * 64;
    const int bm = blockIdx.y * 128;
    const int bn = blockIdx.x * 128;

    float acc[4][8][4];
    #pragma unroll
    for (int i = 0; i < 4; i++)
        #pragma unroll
        for (int j = 0; j < 8; j++)
            #pragma unroll
            for (int q = 0; q < 4; q++) acc[i][j][q] = 0.f;

    const int NK = K / 16;

    #define G_LOAD(s, k0)                                                        \
    {                                                                            \
        float* as_ = As + (s)*GSS;                                               \
        float* bs_ = Bs + (s)*GSB;                                               \
        _Pragma("unroll")                                                        \
        for (int hh = 0; hh < 4; hh++) {                                         \
            int c = tid + hh*128;                                                \
            int row = c >> 2, kc = (c & 3) * 4;                                  \
            unsigned dst = (unsigned)__cvta_generic_to_shared(                   \
                                &as_[row*ASTR + kc]);                            \
            const float* src = A + (size_t)(bm + row)*K + (k0) + kc;             \
            asm volatile("cp.async.ca.shared.global [%0], [%1], 16;"             \
                         :: "r"(dst), "l"(src));                                 \
        }                                                                        \
        _Pragma("unroll")                                                        \
        for (int hh = 0; hh < 4; hh++) {                                         \
            int c = tid + hh*128;                                                \
            int row = c >> 5, col = (c & 31) * 4;                                \
            unsigned dst = (unsigned)__cvta_generic_to_shared(                   \
                                &bs_[row*BSTR + col]);                           \
            const float* src = B + (size_t)((k0) + row)*N + bn + col;            \
            asm volatile("cp.async.ca.shared.global [%0], [%1], 16;"             \
                         :: "r"(dst), "l"(src));                                 \
        }                                                                        \
        asm volatile("cp.async.commit_group;");                                  \
    }

    G_LOAD(0, 0)
    G_LOAD(1, 16)

    for (int kt = 0; kt < NK; kt++) {
        if (kt < NK-1) asm volatile("cp.async.wait_group 1;");
        else           asm volatile("cp.async.wait_group 0;");
        __syncthreads();
        if (kt + 2 < NK) G_LOAD((kt+2)%3, (kt+2)*16)

        const float* as = As + (kt%3)*GSS;
        const float* bs = Bs + (kt%3)*GSB;

        #pragma unroll
        for (int kk = 0; kk < 2; kk++) {
            const int k8 = kk * 8;
            unsigned af[4][4];
            #pragma unroll
            for (int mt = 0; mt < 4; mt++) {
                int m0 = wm + mt*16 + lr;
                af[mt][0] = __float_as_uint(as[(m0    )*ASTR + k8     + lc]);
                af[mt][1] = __float_as_uint(as[(m0 + 8)*ASTR + k8     + lc]);
                af[mt][2] = __float_as_uint(as[(m0    )*ASTR + k8 + 4 + lc]);
                af[mt][3] = __float_as_uint(as[(m0 + 8)*ASTR + k8 + 4 + lc]);
            }
            unsigned bf[8][2];
            #pragma unroll
            for (int nt = 0; nt < 8; nt++) {
                int n0 = wn + nt*8 + lr;
                bf[nt][0] = __float_as_uint(bs[(k8     + lc)*BSTR + n0]);
                bf[nt][1] = __float_as_uint(bs[(k8 + 4 + lc)*BSTR + n0]);
            }
            #pragma unroll
            for (int mt = 0; mt < 4; mt++)
                #pragma unroll
                for (int nt = 0; nt < 8; nt++) {
                    asm volatile(
                        "mma.sync.aligned.m16n8k8.row.col.f32.tf32.tf32.f32 "
                        "{%0,%1,%2,%3},{%4,%5,%6,%7},{%8,%9},{%0,%1,%2,%3};"
                        : "+f"(acc[mt][nt][0]), "+f"(acc[mt][nt][1]),
                          "+f"(acc[mt][nt][2]), "+f"(acc[mt][nt][3])
                        : "r"(af[mt][0]), "r"(af[mt][1]),
                          "r"(af[mt][2]), "r"(af[mt][3]),
                          "r"(bf[nt][0]), "r"(bf[nt][1]));
                }
        }
    }

    #pragma unroll
    for (int mt = 0; mt < 4; mt++) {
        int r0 = bm + wm + mt*16 + lr;
        #pragma unroll
        for (int nt = 0; nt < 8; nt++) {
            int cc = bn + wn + nt*8 + lc*2;
            float2 v0 = make_float2(acc[mt][nt][0], acc[mt][nt][1]);
            float2 v1 = make_float2(acc[mt][nt][2], acc[mt][nt][3]);
            if (roundOut) {
                v0.x = rnd_tf32(v0.x); v0.y = rnd_tf32(v0.y);
                v1.x = rnd_tf32(v1.x); v1.y = rnd_tf32(v1.y);
            }
            *(float2*)&C[(size_t)r0*N + cc]     = v0;
            *(float2*)&C[(size_t)(r0+8)*N + cc] = v1;
        }
    }
}

// ---------------------------------------------------------------------------
// Tensor-core flash attention v2 (tf32 mma.sync).
// Grid (b=8, qt=8, h=16); 128 threads = 4 warps, warp = 32 q-rows.
// Q fragments live in registers (extracted once); its smem buffer is reused
// for P. K/V double-buffered via cp.async (prefetch next tile during mma).
// Inputs (g_qkv) are pre-rounded to tf32 by the QKV GEMM epilogue.
// ---------------------------------------------------------------------------
#define ATP  68
#define ATPV 72
#define A_QP (128*ATP)            // Q staging, then P (per-warp rows)
#define A_KS (64*ATP)             // one K stage
#define A_VS (64*ATPV)            // one V stage
#define ATTN_SMEM ((A_QP + 2*A_KS + 2*A_VS)*sizeof(float)) // 106496 B

__global__ __launch_bounds__(128) void attn_tc_kernel(const float* __restrict__ bias)
{
    extern __shared__ float sm[];
    float* QP  = sm;                      // [128][ATP]
    float* Ksm = sm + A_QP;               // [2][64][ATP]
    float* Vsm = sm + A_QP + 2*A_KS;      // [2][64][ATPV]

    const int b  = blockIdx.x;
    const int qt = blockIdx.y;
    const int h  = blockIdx.z;
    const int tid  = threadIdx.x;
    const int lane = tid & 31;
    const int warp = tid >> 5;
    const int wq = warp * 32;
    const int lr = lane >> 2, lc = lane & 3;

    const float* qbase = g_qkv + (size_t)(b*NSEQ + qt*128)*QKVW + h*DHEAD;
    const float* kbase = g_qkv + (size_t)(b*NSEQ)*QKVW + INNER   + h*DHEAD;
    const float* vbase = g_qkv + (size_t)(b*NSEQ)*QKVW + 2*INNER + h*DHEAD;
    const float* bb0   = bias + ((size_t)h*NSEQ + qt*128 + wq)*NSEQ;

    // stage Q via cp.async
    #pragma unroll
    for (int p = 0; p < 16; p++) {
        int c = p*128 + tid;
        int row = c >> 4, col = (c & 15) * 4;
        unsigned dst = (unsigned)__cvta_generic_to_shared(&QP[row*ATP + col]);
        const float* src = qbase + (size_t)row*QKVW + col;
        asm volatile("cp.async.ca.shared.global [%0], [%1], 16;"
                     :: "r"(dst), "l"(src));
    }

    #define KV_LOAD(s, ktl)                                                      \
    {                                                                            \
        float* kd = Ksm + (s)*A_KS;                                              \
        float* vd = Vsm + (s)*A_VS;                                              \
        _Pragma("unroll")                                                        \
        for (int p = 0; p < 8; p++) {                                            \
            int c = p*128 + tid;                                                 \
            int row = c >> 4, col = (c & 15) * 4;                                \
            unsigned dk = (unsigned)__cvta_generic_to_shared(&kd[row*ATP + col]);\
            const float* sk = kbase + (size_t)((ktl)*64 + row)*QKVW + col;       \
            asm volatile("cp.async.ca.shared.global [%0], [%1], 16;"             \
                         :: "r"(dk), "l"(sk));                                   \
            unsigned dv = (unsigned)__cvta_generic_to_shared(&vd[row*ATPV+col]); \
            const float* sv = vbase + (size_t)((ktl)*64 + row)*QKVW + col;       \
            asm volatile("cp.async.ca.shared.global [%0], [%1], 16;"             \
                         :: "r"(dv), "l"(sv));                                   \
        }                                                                        \
    }

    KV_LOAD(0, 0)
    asm volatile("cp.async.commit_group;");
    asm volatile("cp.async.wait_group 0;");
    __syncthreads();

    // extract Q fragments to registers (scaled by 1/8, exact in tf32)
    unsigned qf[8][2][4];
    #pragma unroll
    for (int k = 0; k < 8; k++) {
        int k8 = k*8;
        #pragma unroll
        for (int mt = 0; mt < 2; mt++) {
            int r0 = wq + mt*16 + lr;
            qf[k][mt][0] = __float_as_uint(QP[(r0    )*ATP + k8     + lc] * 0.125f);
            qf[k][mt][1] = __float_as_uint(QP[(r0 + 8)*ATP + k8     + lc] * 0.125f);
            qf[k][mt][2] = __float_as_uint(QP[(r0    )*ATP + k8 + 4 + lc] * 0.125f);
            qf[k][mt][3] = __float_as_uint(QP[(r0 + 8)*ATP + k8 + 4 + lc] * 0.125f);
        }
    }
    __syncthreads();

    float m[4], l[4];
    float co[2][8][4];
    #pragma unroll
    for (int i = 0; i < 4; i++) { m[i] = -1e30f; l[i] = 0.f; }
    #pragma unroll
    for (int mt = 0; mt < 2; mt++)
        #pragma unroll
        for (int nt = 0; nt < 8; nt++)
            #pragma unroll
            for (int q = 0; q < 4; q++) co[mt][nt][q] = 0.f;

    for (int kt = 0; kt < 16; kt++) {
        asm volatile("cp.async.wait_group 0;");
        __syncthreads();
        if (kt < 15) {
            KV_LOAD((kt+1)&1, kt+1)
            asm volatile("cp.async.commit_group;");
        }
        const float* Ks = Ksm + (kt&1)*A_KS;
        const float* Vs = Vsm + (kt&1)*A_VS;

        // S accum initialized with bias
        float cs[2][8][4];
        const float* bb = bb0 + kt*64;
        #pragma unroll
        for (int mt = 0; mt < 2; mt++)
            #pragma unroll
            for (int hh = 0; hh < 2; hh++) {
                int roff = mt*16 + lr + 8*hh;
                #pragma unroll
                for (int nt = 0; nt < 8; nt++) {
                    float2 t = *(const float2*)(bb + (size_t)roff*NSEQ + nt*8 + 2*lc);
                    cs[mt][nt][2*hh]   = t.x;
                    cs[mt][nt][2*hh+1] = t.y;
                }
            }

        // S = Q K^T + bias  (A from registers, B from Ks)
        #pragma unroll
        for (int k = 0; k < 8; k++) {
            int k8 = k*8;
            unsigned bf[8][2];
            #pragma unroll
            for (int nt = 0; nt < 8; nt++) {
                int n0 = nt*8 + lr;
                bf[nt][0] = __float_as_uint(Ks[n0*ATP + k8     + lc]);
                bf[nt][1] = __float_as_uint(Ks[n0*ATP + k8 + 4 + lc]);
            }
            #pragma unroll
            for (int mt = 0; mt < 2; mt++)
                #pragma unroll
                for (int nt = 0; nt < 8; nt++) {
                    asm volatile(
                        "mma.sync.aligned.m16n8k8.row.col.f32.tf32.tf32.f32 "
                        "{%0,%1,%2,%3},{%4,%5,%6,%7},{%8,%9},{%0,%1,%2,%3};"
                        : "+f"(cs[mt][nt][0]), "+f"(cs[mt][nt][1]),
                          "+f"(cs[mt][nt][2]), "+f"(cs[mt][nt][3])
                        : "r"(qf[k][mt][0]), "r"(qf[k][mt][1]),
                          "r"(qf[k][mt][2]), "r"(qf[k][mt][3]),
                          "r"(bf[nt][0]), "r"(bf[nt][1]));
                }
        }

        // online softmax; P -> QP (aliased, per-warp rows), tf32-rounded
        #pragma unroll
        for (int mt = 0; mt < 2; mt++)
            #pragma unroll
            for (int hh = 0; hh < 2; hh++) {
                int idx = mt*2 + hh;
                float mx = -1e30f;
                #pragma unroll
                for (int nt = 0; nt < 8; nt++)
                    mx = fmaxf(mx, fmaxf(cs[mt][nt][2*hh], cs[mt][nt][2*hh+1]));
                mx = fmaxf(mx, __shfl_xor_sync(0xFFFFFFFFu, mx, 1));
                mx = fmaxf(mx, __shfl_xor_sync(0xFFFFFFFFu, mx, 2));
                float mnew = fmaxf(m[idx], mx);
                float corr = __expf(m[idx] - mnew);
                m[idx] = mnew;
                float ls = 0.f;
                int prow = (wq + mt*16 + lr + 8*hh)*ATP + 2*lc;
                #pragma unroll
                for (int nt = 0; nt < 8; nt++) {
                    float p0 = __expf(cs[mt][nt][2*hh]   - mnew);
                    float p1 = __expf(cs[mt][nt][2*hh+1] - mnew);
                    ls += p0 + p1;
                    float2 pv2 = make_float2(rnd_tf32(p0), rnd_tf32(p1));
                    *(float2*)&QP[prow + nt*8] = pv2;
                }
                ls += __shfl_xor_sync(0xFFFFFFFFu, ls, 1);
                ls += __shfl_xor_sync(0xFFFFFFFFu, ls, 2);
                l[idx] = l[idx]*corr + ls;
                #pragma unroll
                for (int nt = 0; nt < 8; nt++) {
                    co[mt][nt][2*hh]   *= corr;
                    co[mt][nt][2*hh+1] *= corr;
                }
            }
        __syncwarp();

        // O += P V
        #pragma unroll
        for (int k = 0; k < 8; k++) {
            int k8 = k*8;
            unsigned af[2][4];
            #pragma unroll
            for (int mt = 0; mt < 2; mt++) {
                int r0 = wq + mt*16 + lr;
                af[mt][0] = __float_as_uint(QP[(r0    )*ATP + k8     + lc]);
                af[mt][1] = __float_as_uint(QP[(r0 + 8)*ATP + k8     + lc]);
                af[mt][2] = __float_as_uint(QP[(r0    )*ATP + k8 + 4 + lc]);
                af[mt][3] = __float_as_uint(QP[(r0 + 8)*ATP + k8 + 4 + lc]);
            }
            unsigned bf[8][2];
            #pragma unroll
            for (int nt = 0; nt < 8; nt++) {
                int n0 = nt*8 + lr;
                bf[nt][0] = __float_as_uint(Vs[(k8     + lc)*ATPV + n0]);
                bf[nt][1] = __float_as_uint(Vs[(k8 + 4 + lc)*ATPV + n0]);
            }
            #pragma unroll
            for (int mt = 0; mt < 2; mt++)
                #pragma unroll
                for (int nt = 0; nt < 8; nt++) {
                    asm volatile(
                        "mma.sync.aligned.m16n8k8.row.col.f32.tf32.tf32.f32 "
                        "{%0,%1,%2,%3},{%4,%5,%6,%7},{%8,%9},{%0,%1,%2,%3};"
                        : "+f"(co[mt][nt][0]), "+f"(co[mt][nt][1]),
                          "+f"(co[mt][nt][2]), "+f"(co[mt][nt][3])
                        : "r"(af[mt][0]), "r"(af[mt][1]),
                          "r"(af[mt][2]), "r"(af[mt][3]),
                          "r"(bf[nt][0]), "r"(bf[nt][1]));
                }
        }
    }

    // epilogue: normalize, round to tf32, write [b,n,(h d)]
    #pragma unroll
    for (int mt = 0; mt < 2; mt++)
        #pragma unroll
        for (int hh = 0; hh < 2; hh++) {
            int idx = mt*2 + hh;
            float inv = 1.0f / l[idx];
            size_t grow = (size_t)(b*NSEQ + qt*128 + wq + mt*16 + lr + 8*hh);
            #pragma unroll
            for (int nt = 0; nt < 8; nt++) {
                float2 o;
                o.x = rnd_tf32(co[mt][nt][2*hh]   * inv);
                o.y = rnd_tf32(co[mt][nt][2*hh+1] * inv);
                *(float2*)&g_att[grow*INNER + h*DHEAD + nt*8 + 2*lc] = o;
            }
        }
}

// ---------------------------------------------------------------------------
extern "C" void kernel_launch(void* const* d_in, const int* in_sizes, int n_in,
                              void* d_out, int out_size)
{
    const float* x     = (const float*)d_in[0];
    const float* gamma = (const float*)d_in[1];
    const float* beta  = (const float*)d_in[2];
    const float* wqkv  = (const float*)d_in[3];
    const float* wout  = (const float*)d_in[4];
    const float* bias  = (const float*)d_in[5];
    float* out = (float*)d_out;

    float *xn, *qkv, *att, *wqkv_t, *wout_t;
    cudaGetSymbolAddress((void**)&xn,     g_xn);
    cudaGetSymbolAddress((void**)&qkv,    g_qkv);
    cudaGetSymbolAddress((void**)&att,    g_att);
    cudaGetSymbolAddress((void**)&wqkv_t, g_wqkv);
    cudaGetSymbolAddress((void**)&wout_t, g_wout);

    cudaFuncSetAttribute(gemm_tf32,
                         cudaFuncAttributeMaxDynamicSharedMemorySize,
                         (int)GEMM_SMEM);
    cudaFuncSetAttribute(attn_tc_kernel,
                         cudaFuncAttributeMaxDynamicSharedMemorySize,
                         (int)ATTN_SMEM);

    round_tf32_kernel<<<(DIM*QKVW/4 + 255)/256, 256>>>(wqkv, wqkv_t, DIM*QKVW/4);
    round_tf32_kernel<<<(INNER*DIM/4 + 255)/256, 256>>>(wout, wout_t, INNER*DIM/4);
    ln_kernel<<<ROWS, 256>>>(x, gamma, beta);
    gemm_tf32<<<dim3(QKVW/128, ROWS/128), 128, GEMM_SMEM>>>(
        xn, wqkv_t, qkv, ROWS, QKVW, DIM, 1);
    attn_tc_kernel<<<dim3(BATCH, NSEQ/128, HEADS), 128, ATTN_SMEM>>>(bias);
    gemm_tf32<<<dim3(DIM/128, ROWS/128), 128, GEMM_SMEM>>>(
        att, wout_t, out, ROWS, DIM, INNER, 0);
}

// round 5
// speedup vs baseline: 3.6462x; 1.0027x over previous
#include <cuda_runtime.h>
#include <math.h>

#define BATCH   8
#define NSEQ    1024
#define DIM     1024
#define HEADS   16
#define DHEAD   64
#define INNER   1024
#define ROWS    (BATCH*NSEQ)   // 8192
#define QKVW    (3*INNER)      // 3072

// Scratch (device globals: allocation-free per harness rules)
__device__ float g_xn  [ROWS*DIM];     // tf32-rounded
__device__ float g_qkv [ROWS*QKVW];    // tf32-rounded (gemm epilogue rounds)
__device__ float g_att [ROWS*INNER];   // tf32-rounded
__device__ float g_wqkv[DIM*QKVW];     // tf32-rounded
__device__ float g_wout[INNER*DIM];    // tf32-rounded

__device__ __forceinline__ unsigned f2tf32(float f) {
    unsigned u;
    asm("cvt.rna.tf32.f32 %0, %1;" : "=r"(u) : "f"(f));
    return u;
}
__device__ __forceinline__ float rnd_tf32(float f) {
    return __uint_as_float(f2tf32(f));
}

#define LDMX4(r0,r1,r2,r3,addr)                                              \
    asm volatile("ldmatrix.sync.aligned.m8n8.x4.shared.b16 "                 \
                 "{%0,%1,%2,%3}, [%4];"                                      \
                 : "=r"(r0), "=r"(r1), "=r"(r2), "=r"(r3) : "r"(addr))

#define MMA_TF32(c0,c1,c2,c3,a0,a1,a2,a3,b0,b1)                              \
    asm volatile(                                                            \
        "mma.sync.aligned.m16n8k8.row.col.f32.tf32.tf32.f32 "                \
        "{%0,%1,%2,%3},{%4,%5,%6,%7},{%8,%9},{%0,%1,%2,%3};"                 \
        : "+f"(c0), "+f"(c1), "+f"(c2), "+f"(c3)                             \
        : "r"(a0), "r"(a1), "r"(a2), "r"(a3), "r"(b0), "r"(b1))

// ---------------------------------------------------------------------------
// Round an fp32 array to tf32 (rna) — for constant weights.
// ---------------------------------------------------------------------------
__global__ __launch_bounds__(256) void round_tf32_kernel(
    const float* __restrict__ in, float* __restrict__ out, int n4)
{
    int i = blockIdx.x * 256 + threadIdx.x;
    if (i < n4) {
        float4 v = ((const float4*)in)[i];
        v.x = rnd_tf32(v.x); v.y = rnd_tf32(v.y);
        v.z = rnd_tf32(v.z); v.w = rnd_tf32(v.w);
        ((float4*)out)[i] = v;
    }
}

// ---------------------------------------------------------------------------
// LayerNorm: one block per row; output rounded to tf32 (feeds tf32 GEMM).
// ---------------------------------------------------------------------------
__global__ __launch_bounds__(256) void ln_kernel(
    const float* __restrict__ x, const float* __restrict__ gamma,
    const float* __restrict__ beta)
{
    int row = blockIdx.x;
    int t = threadIdx.x;
    const float4 v = ((const float4*)(x + (size_t)row*DIM))[t];

    float s  = v.x + v.y + v.z + v.w;
    float ss = v.x*v.x + v.y*v.y + v.z*v.z + v.w*v.w;
    #pragma unroll
    for (int o = 16; o > 0; o >>= 1) {
        s  += __shfl_xor_sync(0xFFFFFFFFu, s,  o);
        ss += __shfl_xor_sync(0xFFFFFFFFu, ss, o);
    }
    __shared__ float rs[8], rss[8];
    int w = t >> 5, l = t & 31;
    if (l == 0) { rs[w] = s; rss[w] = ss; }
    __syncthreads();
    if (w == 0) {
        s  = (l < 8) ? rs[l]  : 0.f;
        ss = (l < 8) ? rss[l] : 0.f;
        #pragma unroll
        for (int o = 4; o > 0; o >>= 1) {
            s  += __shfl_xor_sync(0xFFFFFFFFu, s,  o);
            ss += __shfl_xor_sync(0xFFFFFFFFu, ss, o);
        }
        if (l == 0) { rs[0] = s; rss[0] = ss; }
    }
    __syncthreads();
    float mu  = rs[0]  * (1.0f/DIM);
    float var = rss[0] * (1.0f/DIM) - mu*mu;
    float inv = rsqrtf(var + 1e-5f);

    const float4 g = ((const float4*)gamma)[t];
    const float4 b = ((const float4*)beta)[t];
    float4 r;
    r.x = rnd_tf32((v.x - mu)*inv*g.x + b.x);
    r.y = rnd_tf32((v.y - mu)*inv*g.y + b.y);
    r.z = rnd_tf32((v.z - mu)*inv*g.z + b.z);
    r.w = rnd_tf32((v.w - mu)*inv*g.w + b.w);
    ((float4*)(g_xn + (size_t)row*DIM))[t] = r;
}

// ---------------------------------------------------------------------------
// TF32 GEMM v3: 128x128x16 block, 4 warps, 64x64 warp tile, 3-stage cp.async.
// A fragments via ldmatrix.x4 (As m-major, pitch 20 -> conflict-free).
// B fragments scalar LDS (Bs k-major, pitch 136 -> conflict-free).
// ---------------------------------------------------------------------------
#define ASTR 20
#define BSTR 136
#define GSS (128*ASTR)
#define GSB (16*BSTR)
#define GEMM_SMEM (3*(GSS+GSB)*sizeof(float))  // 56832 B

__global__ __launch_bounds__(128) void gemm_tf32(
    const float* __restrict__ A, const float* __restrict__ B,
    float* __restrict__ C, int M, int N, int K, int roundOut)
{
    extern __shared__ float gsm[];
    float* As = gsm;
    float* Bs = gsm + 3*GSS;

    const int tid  = threadIdx.x;
    const int lane = tid & 31;
    const int warp = tid >> 5;
    const int lr = lane >> 2, lc = lane & 3;
    const int g8 = lane >> 3;                   // ldmatrix group
    const int i8 = lane & 7;
    const int wm = (warp & 1) * 64;
    const int wn = (warp >> 1) * 64;
    const int bm = blockIdx.y * 128;
    const int bn = blockIdx.x * 128;

    // ldmatrix per-thread element offsets (A-side mapping):
    // matrix0 rows 0-7 k-lo, m1 rows 8-15 k-lo, m2 rows 0-7 k-hi, m3 rows 8-15 k-hi
    int aoff[4];
    #pragma unroll
    for (int mt = 0; mt < 4; mt++)
        aoff[mt] = ((wm + mt*16 + (g8 & 1)*8 + i8)*ASTR + (g8 >> 1)*4) * 4;

    float acc[4][8][4];
    #pragma unroll
    for (int i = 0; i < 4; i++)
        #pragma unroll
        for (int j = 0; j < 8; j++)
            #pragma unroll
            for (int q = 0; q < 4; q++) acc[i][j][q] = 0.f;

    const int NK = K / 16;

    #define G_LOAD(s, k0)                                                        \
    {                                                                            \
        float* as_ = As + (s)*GSS;                                               \
        float* bs_ = Bs + (s)*GSB;                                               \
        _Pragma("unroll")                                                        \
        for (int hh = 0; hh < 4; hh++) {                                         \
            int c = tid + hh*128;                                                \
            int row = c >> 2, kc = (c & 3) * 4;                                  \
            unsigned dst = (unsigned)__cvta_generic_to_shared(                   \
                                &as_[row*ASTR + kc]);                            \
            const float* src = A + (size_t)(bm + row)*K + (k0) + kc;             \
            asm volatile("cp.async.ca.shared.global [%0], [%1], 16;"             \
                         :: "r"(dst), "l"(src));                                 \
        }                                                                        \
        _Pragma("unroll")                                                        \
        for (int hh = 0; hh < 4; hh++) {                                         \
            int c = tid + hh*128;                                                \
            int row = c >> 5, col = (c & 31) * 4;                                \
            unsigned dst = (unsigned)__cvta_generic_to_shared(                   \
                                &bs_[row*BSTR + col]);                           \
            const float* src = B + (size_t)((k0) + row)*N + bn + col;            \
            asm volatile("cp.async.ca.shared.global [%0], [%1], 16;"             \
                         :: "r"(dst), "l"(src));                                 \
        }                                                                        \
        asm volatile("cp.async.commit_group;");                                  \
    }

    G_LOAD(0, 0)
    G_LOAD(1, 16)

    for (int kt = 0; kt < NK; kt++) {
        if (kt < NK-1) asm volatile("cp.async.wait_group 1;");
        else           asm volatile("cp.async.wait_group 0;");
        __syncthreads();
        if (kt + 2 < NK) G_LOAD((kt+2)%3, (kt+2)*16)

        const float* as = As + (kt%3)*GSS;
        const float* bs = Bs + (kt%3)*GSB;
        unsigned aBase = (unsigned)__cvta_generic_to_shared(as);

        #pragma unroll
        for (int kk = 0; kk < 2; kk++) {
            const int k8 = kk * 8;
            unsigned af[4][4];
            #pragma unroll
            for (int mt = 0; mt < 4; mt++)
                LDMX4(af[mt][0], af[mt][1], af[mt][2], af[mt][3],
                      aBase + aoff[mt] + k8*4);
            unsigned bf[8][2];
            #pragma unroll
            for (int nt = 0; nt < 8; nt++) {
                int n0 = wn + nt*8 + lr;
                bf[nt][0] = __float_as_uint(bs[(k8     + lc)*BSTR + n0]);
                bf[nt][1] = __float_as_uint(bs[(k8 + 4 + lc)*BSTR + n0]);
            }
            #pragma unroll
            for (int mt = 0; mt < 4; mt++)
                #pragma unroll
                for (int nt = 0; nt < 8; nt++)
                    MMA_TF32(acc[mt][nt][0], acc[mt][nt][1],
                             acc[mt][nt][2], acc[mt][nt][3],
                             af[mt][0], af[mt][1], af[mt][2], af[mt][3],
                             bf[nt][0], bf[nt][1]);
        }
    }

    #pragma unroll
    for (int mt = 0; mt < 4; mt++) {
        int r0 = bm + wm + mt*16 + lr;
        #pragma unroll
        for (int nt = 0; nt < 8; nt++) {
            int cc = bn + wn + nt*8 + lc*2;
            float2 v0 = make_float2(acc[mt][nt][0], acc[mt][nt][1]);
            float2 v1 = make_float2(acc[mt][nt][2], acc[mt][nt][3]);
            if (roundOut) {
                v0.x = rnd_tf32(v0.x); v0.y = rnd_tf32(v0.y);
                v1.x = rnd_tf32(v1.x); v1.y = rnd_tf32(v1.y);
            }
            *(float2*)&C[(size_t)r0*N + cc]     = v0;
            *(float2*)&C[(size_t)(r0+8)*N + cc] = v1;
        }
    }
}

// ---------------------------------------------------------------------------
// Tensor-core flash attention v3 (tf32 mma.sync + ldmatrix).
// Grid (b=8, qt=8, h=16); 128 threads = 4 warps, warp = 32 q-rows.
// Q fragments in registers; QP smem reused for P (ldmatrix A-side loads).
// K tile is n-major/k-contiguous -> B-side fragments via ldmatrix.x4.
// K/V double-buffered via cp.async. V via scalar LDS (k-major).
// ---------------------------------------------------------------------------
#define ATP  68
#define ATPV 72
#define A_QP (128*ATP)
#define A_KS (64*ATP)
#define A_VS (64*ATPV)
#define ATTN_SMEM ((A_QP + 2*A_KS + 2*A_VS)*sizeof(float)) // 106496 B

__global__ __launch_bounds__(128) void attn_tc_kernel(const float* __restrict__ bias)
{
    extern __shared__ float sm[];
    float* QP  = sm;                      // [128][ATP]
    float* Ksm = sm + A_QP;               // [2][64][ATP]
    float* Vsm = sm + A_QP + 2*A_KS;      // [2][64][ATPV]

    const int b  = blockIdx.x;
    const int qt = blockIdx.y;
    const int h  = blockIdx.z;
    const int tid  = threadIdx.x;
    const int lane = tid & 31;
    const int warp = tid >> 5;
    const int wq = warp * 32;
    const int lr = lane >> 2, lc = lane & 3;
    const int g8 = lane >> 3;
    const int i8 = lane & 7;

    const float* qbase = g_qkv + (size_t)(b*NSEQ + qt*128)*QKVW + h*DHEAD;
    const float* kbase = g_qkv + (size_t)(b*NSEQ)*QKVW + INNER   + h*DHEAD;
    const float* vbase = g_qkv + (size_t)(b*NSEQ)*QKVW + 2*INNER + h*DHEAD;
    const float* bb0   = bias + ((size_t)h*NSEQ + qt*128 + wq)*NSEQ;

    // ldmatrix per-thread element offsets
    // P (A-side): m0 rows0-7 klo, m1 rows8-15 klo, m2 rows0-7 khi, m3 rows8-15 khi
    int poff[2];
    #pragma unroll
    for (int mt = 0; mt < 2; mt++)
        poff[mt] = ((wq + mt*16 + (g8 & 1)*8 + i8)*ATP + (g8 >> 1)*4) * 4;
    // K (B-side): m0 nt0 klo, m1 nt0 khi, m2 nt1 klo, m3 nt1 khi
    int koff[4];
    #pragma unroll
    for (int ntp = 0; ntp < 4; ntp++)
        koff[ntp] = ((ntp*16 + ((g8 >> 1) & 1)*8 + i8)*ATP + (g8 & 1)*4) * 4;

    unsigned qpBase = (unsigned)__cvta_generic_to_shared(QP);

    // stage Q via cp.async
    #pragma unroll
    for (int p = 0; p < 16; p++) {
        int c = p*128 + tid;
        int row = c >> 4, col = (c & 15) * 4;
        unsigned dst = (unsigned)__cvta_generic_to_shared(&QP[row*ATP + col]);
        const float* src = qbase + (size_t)row*QKVW + col;
        asm volatile("cp.async.ca.shared.global [%0], [%1], 16;"
                     :: "r"(dst), "l"(src));
    }

    #define KV_LOAD(s, ktl)                                                      \
    {                                                                            \
        float* kd = Ksm + (s)*A_KS;                                              \
        float* vd = Vsm + (s)*A_VS;                                              \
        _Pragma("unroll")                                                        \
        for (int p = 0; p < 8; p++) {                                            \
            int c = p*128 + tid;                                                 \
            int row = c >> 4, col = (c & 15) * 4;                                \
            unsigned dk = (unsigned)__cvta_generic_to_shared(&kd[row*ATP + col]);\
            const float* sk = kbase + (size_t)((ktl)*64 + row)*QKVW + col;       \
            asm volatile("cp.async.ca.shared.global [%0], [%1], 16;"             \
                         :: "r"(dk), "l"(sk));                                   \
            unsigned dv = (unsigned)__cvta_generic_to_shared(&vd[row*ATPV+col]); \
            const float* sv = vbase + (size_t)((ktl)*64 + row)*QKVW + col;       \
            asm volatile("cp.async.ca.shared.global [%0], [%1], 16;"             \
                         :: "r"(dv), "l"(sv));                                   \
        }                                                                        \
    }

    KV_LOAD(0, 0)
    asm volatile("cp.async.commit_group;");
    asm volatile("cp.async.wait_group 0;");
    __syncthreads();

    // extract Q fragments to registers (scaled by 1/8, exact in tf32)
    unsigned qf[8][2][4];
    #pragma unroll
    for (int k = 0; k < 8; k++) {
        int k8 = k*8;
        #pragma unroll
        for (int mt = 0; mt < 2; mt++) {
            int r0 = wq + mt*16 + lr;
            qf[k][mt][0] = __float_as_uint(QP[(r0    )*ATP + k8     + lc] * 0.125f);
            qf[k][mt][1] = __float_as_uint(QP[(r0 + 8)*ATP + k8     + lc] * 0.125f);
            qf[k][mt][2] = __float_as_uint(QP[(r0    )*ATP + k8 + 4 + lc] * 0.125f);
            qf[k][mt][3] = __float_as_uint(QP[(r0 + 8)*ATP + k8 + 4 + lc] * 0.125f);
        }
    }
    __syncthreads();

    float m[4], l[4];
    float co[2][8][4];
    #pragma unroll
    for (int i = 0; i < 4; i++) { m[i] = -1e30f; l[i] = 0.f; }
    #pragma unroll
    for (int mt = 0; mt < 2; mt++)
        #pragma unroll
        for (int nt = 0; nt < 8; nt++)
            #pragma unroll
            for (int q = 0; q < 4; q++) co[mt][nt][q] = 0.f;

    for (int kt = 0; kt < 16; kt++) {
        asm volatile("cp.async.wait_group 0;");
        __syncthreads();
        if (kt < 15) {
            KV_LOAD((kt+1)&1, kt+1)
            asm volatile("cp.async.commit_group;");
        }
        const float* Vs = Vsm + (kt&1)*A_VS;
        unsigned kBase = (unsigned)__cvta_generic_to_shared(Ksm + (kt&1)*A_KS);

        // S accum initialized with bias
        float cs[2][8][4];
        const float* bb = bb0 + kt*64;
        #pragma unroll
        for (int mt = 0; mt < 2; mt++)
            #pragma unroll
            for (int hh = 0; hh < 2; hh++) {
                int roff = mt*16 + lr + 8*hh;
                #pragma unroll
                for (int nt = 0; nt < 8; nt++) {
                    float2 t = *(const float2*)(bb + (size_t)roff*NSEQ + nt*8 + 2*lc);
                    cs[mt][nt][2*hh]   = t.x;
                    cs[mt][nt][2*hh+1] = t.y;
                }
            }

        // S = Q K^T + bias  (A regs, B via ldmatrix)
        #pragma unroll
        for (int k = 0; k < 8; k++) {
            int k8 = k*8;
            unsigned bf[8][2];
            #pragma unroll
            for (int ntp = 0; ntp < 4; ntp++)
                LDMX4(bf[2*ntp][0], bf[2*ntp][1], bf[2*ntp+1][0], bf[2*ntp+1][1],
                      kBase + koff[ntp] + k8*4);
            #pragma unroll
            for (int mt = 0; mt < 2; mt++)
                #pragma unroll
                for (int nt = 0; nt < 8; nt++)
                    MMA_TF32(cs[mt][nt][0], cs[mt][nt][1],
                             cs[mt][nt][2], cs[mt][nt][3],
                             qf[k][mt][0], qf[k][mt][1],
                             qf[k][mt][2], qf[k][mt][3],
                             bf[nt][0], bf[nt][1]);
        }

        // online softmax; P -> QP (aliased, per-warp rows), tf32-rounded
        #pragma unroll
        for (int mt = 0; mt < 2; mt++)
            #pragma unroll
            for (int hh = 0; hh < 2; hh++) {
                int idx = mt*2 + hh;
                float mx = -1e30f;
                #pragma unroll
                for (int nt = 0; nt < 8; nt++)
                    mx = fmaxf(mx, fmaxf(cs[mt][nt][2*hh], cs[mt][nt][2*hh+1]));
                mx = fmaxf(mx, __shfl_xor_sync(0xFFFFFFFFu, mx, 1));
                mx = fmaxf(mx, __shfl_xor_sync(0xFFFFFFFFu, mx, 2));
                float mnew = fmaxf(m[idx], mx);
                float corr = __expf(m[idx] - mnew);
                m[idx] = mnew;
                float ls = 0.f;
                int prow = (wq + mt*16 + lr + 8*hh)*ATP + 2*lc;
                #pragma unroll
                for (int nt = 0; nt < 8; nt++) {
                    float p0 = __expf(cs[mt][nt][2*hh]   - mnew);
                    float p1 = __expf(cs[mt][nt][2*hh+1] - mnew);
                    ls += p0 + p1;
                    float2 pv2 = make_float2(rnd_tf32(p0), rnd_tf32(p1));
                    *(float2*)&QP[prow + nt*8] = pv2;
                }
                ls += __shfl_xor_sync(0xFFFFFFFFu, ls, 1);
                ls += __shfl_xor_sync(0xFFFFFFFFu, ls, 2);
                l[idx] = l[idx]*corr + ls;
                #pragma unroll
                for (int nt = 0; nt < 8; nt++) {
                    co[mt][nt][2*hh]   *= corr;
                    co[mt][nt][2*hh+1] *= corr;
                }
            }
        __syncwarp();

        // O += P V  (P via ldmatrix, V scalar LDS)
        #pragma unroll
        for (int k = 0; k < 8; k++) {
            int k8 = k*8;
            unsigned af[2][4];
            #pragma unroll
            for (int mt = 0; mt < 2; mt++)
                LDMX4(af[mt][0], af[mt][1], af[mt][2], af[mt][3],
                      qpBase + poff[mt] + k8*4);
            unsigned bf[8][2];
            #pragma unroll
            for (int nt = 0; nt < 8; nt++) {
                int n0 = nt*8 + lr;
                bf[nt][0] = __float_as_uint(Vs[(k8     + lc)*ATPV + n0]);
                bf[nt][1] = __float_as_uint(Vs[(k8 + 4 + lc)*ATPV + n0]);
            }
            #pragma unroll
            for (int mt = 0; mt < 2; mt++)
                #pragma unroll
                for (int nt = 0; nt < 8; nt++)
                    MMA_TF32(co[mt][nt][0], co[mt][nt][1],
                             co[mt][nt][2], co[mt][nt][3],
                             af[mt][0], af[mt][1], af[mt][2], af[mt][3],
                             bf[nt][0], bf[nt][1]);
        }
    }

    // epilogue: normalize, round to tf32, write [b,n,(h d)]
    #pragma unroll
    for (int mt = 0; mt < 2; mt++)
        #pragma unroll
        for (int hh = 0; hh < 2; hh++) {
            int idx = mt*2 + hh;
            float inv = 1.0f / l[idx];
            size_t grow = (size_t)(b*NSEQ + qt*128 + wq + mt*16 + lr + 8*hh);
            #pragma unroll
            for (int nt = 0; nt < 8; nt++) {
                float2 o;
                o.x = rnd_tf32(co[mt][nt][2*hh]   * inv);
                o.y = rnd_tf32(co[mt][nt][2*hh+1] * inv);
                *(float2*)&g_att[grow*INNER + h*DHEAD + nt*8 + 2*lc] = o;
            }
        }
}

// ---------------------------------------------------------------------------
extern "C" void kernel_launch(void* const* d_in, const int* in_sizes, int n_in,
                              void* d_out, int out_size)
{
    const float* x     = (const float*)d_in[0];
    const float* gamma = (const float*)d_in[1];
    const float* beta  = (const float*)d_in[2];
    const float* wqkv  = (const float*)d_in[3];
    const float* wout  = (const float*)d_in[4];
    const float* bias  = (const float*)d_in[5];
    float* out = (float*)d_out;

    float *xn, *qkv, *att, *wqkv_t, *wout_t;
    cudaGetSymbolAddress((void**)&xn,     g_xn);
    cudaGetSymbolAddress((void**)&qkv,    g_qkv);
    cudaGetSymbolAddress((void**)&att,    g_att);
    cudaGetSymbolAddress((void**)&wqkv_t, g_wqkv);
    cudaGetSymbolAddress((void**)&wout_t, g_wout);

    cudaFuncSetAttribute(gemm_tf32,
                         cudaFuncAttributeMaxDynamicSharedMemorySize,
                         (int)GEMM_SMEM);
    cudaFuncSetAttribute(attn_tc_kernel,
                         cudaFuncAttributeMaxDynamicSharedMemorySize,
                         (int)ATTN_SMEM);

    round_tf32_kernel<<<(DIM*QKVW/4 + 255)/256, 256>>>(wqkv, wqkv_t, DIM*QKVW/4);
    round_tf32_kernel<<<(INNER*DIM/4 + 255)/256, 256>>>(wout, wout_t, INNER*DIM/4);
    ln_kernel<<<ROWS, 256>>>(x, gamma, beta);
    gemm_tf32<<<dim3(QKVW/128, ROWS/128), 128, GEMM_SMEM>>>(
        xn, wqkv_t, qkv, ROWS, QKVW, DIM, 1);
    attn_tc_kernel<<<dim3(BATCH, NSEQ/128, HEADS), 128, ATTN_SMEM>>>(bias);
    gemm_tf32<<<dim3(DIM/128, ROWS/128), 128, GEMM_SMEM>>>(
        att, wout_t, out, ROWS, DIM, INNER, 0);
}

// round 7
// speedup vs baseline: 3.7871x; 1.0386x over previous
#include <cuda_runtime.h>
#include <stdint.h>
#include <math.h>

#define BATCH   8
#define NSEQ    1024
#define DIM     1024
#define HEADS   16
#define DHEAD   64
#define INNER   1024
#define ROWS    (BATCH*NSEQ)   // 8192
#define QKVW    (3*INNER)      // 3072

// Scratch (device globals: allocation-free per harness rules)
__device__ float g_xn   [ROWS*DIM];     // tf32-rounded
__device__ float g_qkv  [ROWS*QKVW];    // tf32-rounded (gemm epilogue rounds)
__device__ float g_att  [ROWS*INNER];   // tf32-rounded
__device__ float g_wqkvT[QKVW*DIM];     // W_qkv^T, tf32-rounded  [n][k]
__device__ float g_woutT[DIM*INNER];    // W_out^T, tf32-rounded  [n][k]

__device__ __forceinline__ unsigned f2tf32(float f) {
    unsigned u;
    asm("cvt.rna.tf32.f32 %0, %1;" : "=r"(u) : "f"(f));
    return u;
}
__device__ __forceinline__ float rnd_tf32(float f) {
    return __uint_as_float(f2tf32(f));
}

#define LDMX4(r0,r1,r2,r3,addr)                                              \
    asm volatile("ldmatrix.sync.aligned.m8n8.x4.shared.b16 "                 \
                 "{%0,%1,%2,%3}, [%4];"                                      \
                 : "=r"(r0), "=r"(r1), "=r"(r2), "=r"(r3) : "r"(addr))

#define MMA_TF32(c0,c1,c2,c3,a0,a1,a2,a3,b0,b1)                              \
    asm volatile(                                                            \
        "mma.sync.aligned.m16n8k8.row.col.f32.tf32.tf32.f32 "                \
        "{%0,%1,%2,%3},{%4,%5,%6,%7},{%8,%9},{%0,%1,%2,%3};"                 \
        : "+f"(c0), "+f"(c1), "+f"(c2), "+f"(c3)                             \
        : "r"(a0), "r"(a1), "r"(a2), "r"(a3), "r"(b0), "r"(b1))

// ---------------------------------------------------------------------------
// Weight transpose + tf32 rounding: out[n*K + k] = rnd(in[k*N + n]).
// ---------------------------------------------------------------------------
__global__ __launch_bounds__(256) void transpose_round_kernel(
    const float* __restrict__ in, float* __restrict__ out, int K, int N)
{
    __shared__ float t[32][33];
    int n0 = blockIdx.x * 32, k0 = blockIdx.y * 32;
    int tx = threadIdx.x & 31, ty = threadIdx.x >> 5;
    #pragma unroll
    for (int j = 0; j < 4; j++)
        t[ty + j*8][tx] = in[(size_t)(k0 + ty + j*8)*N + n0 + tx];
    __syncthreads();
    #pragma unroll
    for (int j = 0; j < 4; j++)
        out[(size_t)(n0 + ty + j*8)*K + k0 + tx] = rnd_tf32(t[tx][ty + j*8]);
}

// ---------------------------------------------------------------------------
// LayerNorm: one block per row; output rounded to tf32.
// ---------------------------------------------------------------------------
__global__ __launch_bounds__(256) void ln_kernel(
    const float* __restrict__ x, const float* __restrict__ gamma,
    const float* __restrict__ beta)
{
    int row = blockIdx.x;
    int t = threadIdx.x;
    const float4 v = ((const float4*)(x + (size_t)row*DIM))[t];

    float s  = v.x + v.y + v.z + v.w;
    float ss = v.x*v.x + v.y*v.y + v.z*v.z + v.w*v.w;
    #pragma unroll
    for (int o = 16; o > 0; o >>= 1) {
        s  += __shfl_xor_sync(0xFFFFFFFFu, s,  o);
        ss += __shfl_xor_sync(0xFFFFFFFFu, ss, o);
    }
    __shared__ float rs[8], rss[8];
    int w = t >> 5, l = t & 31;
    if (l == 0) { rs[w] = s; rss[w] = ss; }
    __syncthreads();
    if (w == 0) {
        s  = (l < 8) ? rs[l]  : 0.f;
        ss = (l < 8) ? rss[l] : 0.f;
        #pragma unroll
        for (int o = 4; o > 0; o >>= 1) {
            s  += __shfl_xor_sync(0xFFFFFFFFu, s,  o);
            ss += __shfl_xor_sync(0xFFFFFFFFu, ss, o);
        }
        if (l == 0) { rs[0] = s; rss[0] = ss; }
    }
    __syncthreads();
    float mu  = rs[0]  * (1.0f/DIM);
    float var = rss[0] * (1.0f/DIM) - mu*mu;
    float inv = rsqrtf(var + 1e-5f);

    const float4 g = ((const float4*)gamma)[t];
    const float4 b = ((const float4*)beta)[t];
    float4 r;
    r.x = rnd_tf32((v.x - mu)*inv*g.x + b.x);
    r.y = rnd_tf32((v.y - mu)*inv*g.y + b.y);
    r.z = rnd_tf32((v.z - mu)*inv*g.z + b.z);
    r.w = rnd_tf32((v.w - mu)*inv*g.w + b.w);
    ((float4*)(g_xn + (size_t)row*DIM))[t] = r;
}

// ---------------------------------------------------------------------------
// TF32 GEMM v4: C[M,N] = A[M,K] @ BT[N,K]^T.  128x128x16 block, 4 warps,
// 64x64 warp tile, 3-stage cp.async. BOTH operands n/m-major k-contiguous,
// pitch 20, fragments via ldmatrix.x4 only (8 LDSM + 32 mma per k8).
// ---------------------------------------------------------------------------
#define STR 20
#define GST (128*STR)                       // floats per operand stage
#define GEMM_SMEM (6*GST*sizeof(float))     // 61440 B

__global__ __launch_bounds__(128) void gemm_tf32(
    const float* __restrict__ A, const float* __restrict__ BT,
    float* __restrict__ C, int M, int N, int K, int roundOut)
{
    extern __shared__ float gsm[];
    float* As = gsm;            // 3 stages [128][20]
    float* Bs = gsm + 3*GST;    // 3 stages [128][20]  (rows = n)

    const int tid  = threadIdx.x;
    const int lane = tid & 31;
    const int warp = tid >> 5;
    const int lr = lane >> 2, lc = lane & 3;
    const int g8 = lane >> 3;
    const int i8 = lane & 7;
    const int wm = (warp & 1) * 64;
    const int wn = (warp >> 1) * 64;
    const int bm = blockIdx.y * 128;
    const int bn = blockIdx.x * 128;

    // ldmatrix element offsets (bytes) — proven mappings:
    // A-side: m0 rows+0 klo, m1 rows+8 klo, m2 rows+0 khi, m3 rows+8 khi
    int aoff[4];
    #pragma unroll
    for (int mt = 0; mt < 4; mt++)
        aoff[mt] = ((wm + mt*16 + (g8 & 1)*8 + i8)*STR + (g8 >> 1)*4) * 4;
    // B-side: m0 n+0 klo, m1 n+0 khi, m2 n+8 klo, m3 n+8 khi
    int boff[4];
    #pragma unroll
    for (int np = 0; np < 4; np++)
        boff[np] = ((wn + np*16 + ((g8 >> 1) & 1)*8 + i8)*STR + (g8 & 1)*4) * 4;

    float acc[4][8][4];
    #pragma unroll
    for (int i = 0; i < 4; i++)
        #pragma unroll
        for (int j = 0; j < 8; j++)
            #pragma unroll
            for (int q = 0; q < 4; q++) acc[i][j][q] = 0.f;

    const int NK = K / 16;

    #define G_LOAD(s, k0)                                                        \
    {                                                                            \
        float* as_ = As + (s)*GST;                                               \
        float* bs_ = Bs + (s)*GST;                                               \
        _Pragma("unroll")                                                        \
        for (int hh = 0; hh < 4; hh++) {                                         \
            int c = tid + hh*128;                                                \
            int row = c >> 2, kc = (c & 3) * 4;                                  \
            unsigned da = (unsigned)__cvta_generic_to_shared(                    \
                                &as_[row*STR + kc]);                             \
            const float* sa = A + (size_t)(bm + row)*K + (k0) + kc;              \
            asm volatile("cp.async.ca.shared.global [%0], [%1], 16;"             \
                         :: "r"(da), "l"(sa));                                   \
            unsigned db = (unsigned)__cvta_generic_to_shared(                    \
                                &bs_[row*STR + kc]);                             \
            const float* sbp = BT + (size_t)(bn + row)*K + (k0) + kc;            \
            asm volatile("cp.async.ca.shared.global [%0], [%1], 16;"             \
                         :: "r"(db), "l"(sbp));                                  \
        }                                                                        \
        asm volatile("cp.async.commit_group;");                                  \
    }

    G_LOAD(0, 0)
    G_LOAD(1, 16)

    for (int kt = 0; kt < NK; kt++) {
        if (kt < NK-1) asm volatile("cp.async.wait_group 1;");
        else           asm volatile("cp.async.wait_group 0;");
        __syncthreads();
        if (kt + 2 < NK) G_LOAD((kt+2)%3, (kt+2)*16)

        unsigned aBase = (unsigned)__cvta_generic_to_shared(As + (kt%3)*GST);
        unsigned bBase = (unsigned)__cvta_generic_to_shared(Bs + (kt%3)*GST);

        #pragma unroll
        for (int kk = 0; kk < 2; kk++) {
            const int k8 = kk * 8;
            unsigned af[4][4];
            #pragma unroll
            for (int mt = 0; mt < 4; mt++)
                LDMX4(af[mt][0], af[mt][1], af[mt][2], af[mt][3],
                      aBase + aoff[mt] + k8*4);
            unsigned bf[8][2];
            #pragma unroll
            for (int np = 0; np < 4; np++)
                LDMX4(bf[2*np][0], bf[2*np][1], bf[2*np+1][0], bf[2*np+1][1],
                      bBase + boff[np] + k8*4);
            #pragma unroll
            for (int mt = 0; mt < 4; mt++)
                #pragma unroll
                for (int nt = 0; nt < 8; nt++)
                    MMA_TF32(acc[mt][nt][0], acc[mt][nt][1],
                             acc[mt][nt][2], acc[mt][nt][3],
                             af[mt][0], af[mt][1], af[mt][2], af[mt][3],
                             bf[nt][0], bf[nt][1]);
        }
    }

    #pragma unroll
    for (int mt = 0; mt < 4; mt++) {
        int r0 = bm + wm + mt*16 + lr;
        #pragma unroll
        for (int nt = 0; nt < 8; nt++) {
            int cc = bn + wn + nt*8 + lc*2;
            float2 v0 = make_float2(acc[mt][nt][0], acc[mt][nt][1]);
            float2 v1 = make_float2(acc[mt][nt][2], acc[mt][nt][3]);
            if (roundOut) {
                v0.x = rnd_tf32(v0.x); v0.y = rnd_tf32(v0.y);
                v1.x = rnd_tf32(v1.x); v1.y = rnd_tf32(v1.y);
            }
            *(float2*)&C[(size_t)r0*N + cc]     = v0;
            *(float2*)&C[(size_t)(r0+8)*N + cc] = v1;
        }
    }
}

// ---------------------------------------------------------------------------
// Tensor-core flash attention (tf32 mma.sync + ldmatrix) — R5 version.
// ---------------------------------------------------------------------------
#define ATP  68
#define ATPV 72
#define A_QP (128*ATP)
#define A_KS (64*ATP)
#define A_VS (64*ATPV)
#define ATTN_SMEM ((A_QP + 2*A_KS + 2*A_VS)*sizeof(float)) // 106496 B

__global__ __launch_bounds__(128) void attn_tc_kernel(const float* __restrict__ bias)
{
    extern __shared__ float sm[];
    float* QP  = sm;                      // [128][ATP]
    float* Ksm = sm + A_QP;               // [2][64][ATP]
    float* Vsm = sm + A_QP + 2*A_KS;      // [2][64][ATPV]

    const int b  = blockIdx.x;
    const int qt = blockIdx.y;
    const int h  = blockIdx.z;
    const int tid  = threadIdx.x;
    const int lane = tid & 31;
    const int warp = tid >> 5;
    const int wq = warp * 32;
    const int lr = lane >> 2, lc = lane & 3;
    const int g8 = lane >> 3;
    const int i8 = lane & 7;

    const float* qbase = g_qkv + (size_t)(b*NSEQ + qt*128)*QKVW + h*DHEAD;
    const float* kbase = g_qkv + (size_t)(b*NSEQ)*QKVW + INNER   + h*DHEAD;
    const float* vbase = g_qkv + (size_t)(b*NSEQ)*QKVW + 2*INNER + h*DHEAD;
    const float* bb0   = bias + ((size_t)h*NSEQ + qt*128 + wq)*NSEQ;

    int poff[2];
    #pragma unroll
    for (int mt = 0; mt < 2; mt++)
        poff[mt] = ((wq + mt*16 + (g8 & 1)*8 + i8)*ATP + (g8 >> 1)*4) * 4;
    int koff[4];
    #pragma unroll
    for (int ntp = 0; ntp < 4; ntp++)
        koff[ntp] = ((ntp*16 + ((g8 >> 1) & 1)*8 + i8)*ATP + (g8 & 1)*4) * 4;

    unsigned qpBase = (unsigned)__cvta_generic_to_shared(QP);

    #pragma unroll
    for (int p = 0; p < 16; p++) {
        int c = p*128 + tid;
        int row = c >> 4, col = (c & 15) * 4;
        unsigned dst = (unsigned)__cvta_generic_to_shared(&QP[row*ATP + col]);
        const float* src = qbase + (size_t)row*QKVW + col;
        asm volatile("cp.async.ca.shared.global [%0], [%1], 16;"
                     :: "r"(dst), "l"(src));
    }

    #define KV_LOAD(s, ktl)                                                      \
    {                                                                            \
        float* kd = Ksm + (s)*A_KS;                                              \
        float* vd = Vsm + (s)*A_VS;                                              \
        _Pragma("unroll")                                                        \
        for (int p = 0; p < 8; p++) {                                            \
            int c = p*128 + tid;                                                 \
            int row = c >> 4, col = (c & 15) * 4;                                \
            unsigned dk = (unsigned)__cvta_generic_to_shared(&kd[row*ATP + col]);\
            const float* sk = kbase + (size_t)((ktl)*64 + row)*QKVW + col;       \
            asm volatile("cp.async.ca.shared.global [%0], [%1], 16;"             \
                         :: "r"(dk), "l"(sk));                                   \
            unsigned dv = (unsigned)__cvta_generic_to_shared(&vd[row*ATPV+col]); \
            const float* sv = vbase + (size_t)((ktl)*64 + row)*QKVW + col;       \
            asm volatile("cp.async.ca.shared.global [%0], [%1], 16;"             \
                         :: "r"(dv), "l"(sv));                                   \
        }                                                                        \
    }

    KV_LOAD(0, 0)
    asm volatile("cp.async.commit_group;");
    asm volatile("cp.async.wait_group 0;");
    __syncthreads();

    unsigned qf[8][2][4];
    #pragma unroll
    for (int k = 0; k < 8; k++) {
        int k8 = k*8;
        #pragma unroll
        for (int mt = 0; mt < 2; mt++) {
            int r0 = wq + mt*16 + lr;
            qf[k][mt][0] = __float_as_uint(QP[(r0    )*ATP + k8     + lc] * 0.125f);
            qf[k][mt][1] = __float_as_uint(QP[(r0 + 8)*ATP + k8     + lc] * 0.125f);
            qf[k][mt][2] = __float_as_uint(QP[(r0    )*ATP + k8 + 4 + lc] * 0.125f);
            qf[k][mt][3] = __float_as_uint(QP[(r0 + 8)*ATP + k8 + 4 + lc] * 0.125f);
        }
    }
    __syncthreads();

    float m[4], l[4];
    float co[2][8][4];
    #pragma unroll
    for (int i = 0; i < 4; i++) { m[i] = -1e30f; l[i] = 0.f; }
    #pragma unroll
    for (int mt = 0; mt < 2; mt++)
        #pragma unroll
        for (int nt = 0; nt < 8; nt++)
            #pragma unroll
            for (int q = 0; q < 4; q++) co[mt][nt][q] = 0.f;

    for (int kt = 0; kt < 16; kt++) {
        asm volatile("cp.async.wait_group 0;");
        __syncthreads();
        if (kt < 15) {
            KV_LOAD((kt+1)&1, kt+1)
            asm volatile("cp.async.commit_group;");
        }
        const float* Vs = Vsm + (kt&1)*A_VS;
        unsigned kBase = (unsigned)__cvta_generic_to_shared(Ksm + (kt&1)*A_KS);

        float cs[2][8][4];
        const float* bb = bb0 + kt*64;
        #pragma unroll
        for (int mt = 0; mt < 2; mt++)
            #pragma unroll
            for (int hh = 0; hh < 2; hh++) {
                int roff = mt*16 + lr + 8*hh;
                #pragma unroll
                for (int nt = 0; nt < 8; nt++) {
                    float2 t = *(const float2*)(bb + (size_t)roff*NSEQ + nt*8 + 2*lc);
                    cs[mt][nt][2*hh]   = t.x;
                    cs[mt][nt][2*hh+1] = t.y;
                }
            }

        #pragma unroll
        for (int k = 0; k < 8; k++) {
            int k8 = k*8;
            unsigned bf[8][2];
            #pragma unroll
            for (int ntp = 0; ntp < 4; ntp++)
                LDMX4(bf[2*ntp][0], bf[2*ntp][1], bf[2*ntp+1][0], bf[2*ntp+1][1],
                      kBase + koff[ntp] + k8*4);
            #pragma unroll
            for (int mt = 0; mt < 2; mt++)
                #pragma unroll
                for (int nt = 0; nt < 8; nt++)
                    MMA_TF32(cs[mt][nt][0], cs[mt][nt][1],
                             cs[mt][nt][2], cs[mt][nt][3],
                             qf[k][mt][0], qf[k][mt][1],
                             qf[k][mt][2], qf[k][mt][3],
                             bf[nt][0], bf[nt][1]);
        }

        #pragma unroll
        for (int mt = 0; mt < 2; mt++)
            #pragma unroll
            for (int hh = 0; hh < 2; hh++) {
                int idx = mt*2 + hh;
                float mx = -1e30f;
                #pragma unroll
                for (int nt = 0; nt < 8; nt++)
                    mx = fmaxf(mx, fmaxf(cs[mt][nt][2*hh], cs[mt][nt][2*hh+1]));
                mx = fmaxf(mx, __shfl_xor_sync(0xFFFFFFFFu, mx, 1));
                mx = fmaxf(mx, __shfl_xor_sync(0xFFFFFFFFu, mx, 2));
                float mnew = fmaxf(m[idx], mx);
                float corr = __expf(m[idx] - mnew);
                m[idx] = mnew;
                float ls = 0.f;
                int prow = (wq + mt*16 + lr + 8*hh)*ATP + 2*lc;
                #pragma unroll
                for (int nt = 0; nt < 8; nt++) {
                    float p0 = __expf(cs[mt][nt][2*hh]   - mnew);
                    float p1 = __expf(cs[mt][nt][2*hh+1] - mnew);
                    ls += p0 + p1;
                    float2 pv2 = make_float2(rnd_tf32(p0), rnd_tf32(p1));
                    *(float2*)&QP[prow + nt*8] = pv2;
                }
                ls += __shfl_xor_sync(0xFFFFFFFFu, ls, 1);
                ls += __shfl_xor_sync(0xFFFFFFFFu, ls, 2);
                l[idx] = l[idx]*corr + ls;
                #pragma unroll
                for (int nt = 0; nt < 8; nt++) {
                    co[mt][nt][2*hh]   *= corr;
                    co[mt][nt][2*hh+1] *= corr;
                }
            }
        __syncwarp();

        #pragma unroll
        for (int k = 0; k < 8; k++) {
            int k8 = k*8;
            unsigned af[2][4];
            #pragma unroll
            for (int mt = 0; mt < 2; mt++)
                LDMX4(af[mt][0], af[mt][1], af[mt][2], af[mt][3],
                      qpBase + poff[mt] + k8*4);
            unsigned bf[8][2];
            #pragma unroll
            for (int nt = 0; nt < 8; nt++) {
                int n0 = nt*8 + lr;
                bf[nt][0] = __float_as_uint(Vs[(k8     + lc)*ATPV + n0]);
                bf[nt][1] = __float_as_uint(Vs[(k8 + 4 + lc)*ATPV + n0]);
            }
            #pragma unroll
            for (int mt = 0; mt < 2; mt++)
                #pragma unroll
                for (int nt = 0; nt < 8; nt++)
                    MMA_TF32(co[mt][nt][0], co[mt][nt][1],
                             co[mt][nt][2], co[mt][nt][3],
                             af[mt][0], af[mt][1], af[mt][2], af[mt][3],
                             bf[nt][0], bf[nt][1]);
        }
    }

    #pragma unroll
    for (int mt = 0; mt < 2; mt++)
        #pragma unroll
        for (int hh = 0; hh < 2; hh++) {
            int idx = mt*2 + hh;
            float inv = 1.0f / l[idx];
            size_t grow = (size_t)(b*NSEQ + qt*128 + wq + mt*16 + lr + 8*hh);
            #pragma unroll
            for (int nt = 0; nt < 8; nt++) {
                float2 o;
                o.x = rnd_tf32(co[mt][nt][2*hh]   * inv);
                o.y = rnd_tf32(co[mt][nt][2*hh+1] * inv);
                *(float2*)&g_att[grow*INNER + h*DHEAD + nt*8 + 2*lc] = o;
            }
        }
}

// ---------------------------------------------------------------------------
extern "C" void kernel_launch(void* const* d_in, const int* in_sizes, int n_in,
                              void* d_out, int out_size)
{
    const float* x     = (const float*)d_in[0];
    const float* gamma = (const float*)d_in[1];
    const float* beta  = (const float*)d_in[2];
    const float* wqkv  = (const float*)d_in[3];
    const float* wout  = (const float*)d_in[4];
    const float* bias  = (const float*)d_in[5];
    float* out = (float*)d_out;

    float *xn, *qkv, *att, *wqkvT, *woutT;
    cudaGetSymbolAddress((void**)&xn,    g_xn);
    cudaGetSymbolAddress((void**)&qkv,   g_qkv);
    cudaGetSymbolAddress((void**)&att,   g_att);
    cudaGetSymbolAddress((void**)&wqkvT, g_wqkvT);
    cudaGetSymbolAddress((void**)&woutT, g_woutT);

    cudaFuncSetAttribute(gemm_tf32,
                         cudaFuncAttributeMaxDynamicSharedMemorySize,
                         (int)GEMM_SMEM);
    cudaFuncSetAttribute(attn_tc_kernel,
                         cudaFuncAttributeMaxDynamicSharedMemorySize,
                         (int)ATTN_SMEM);

    transpose_round_kernel<<<dim3(QKVW/32, DIM/32), 256>>>(wqkv, wqkvT, DIM, QKVW);
    transpose_round_kernel<<<dim3(DIM/32, INNER/32), 256>>>(wout, woutT, INNER, DIM);
    ln_kernel<<<ROWS, 256>>>(x, gamma, beta);
    gemm_tf32<<<dim3(QKVW/128, ROWS/128), 128, GEMM_SMEM>>>(
        xn, wqkvT, qkv, ROWS, QKVW, DIM, 1);
    attn_tc_kernel<<<dim3(BATCH, NSEQ/128, HEADS), 128, ATTN_SMEM>>>(bias);
    gemm_tf32<<<dim3(DIM/128, ROWS/128), 128, GEMM_SMEM>>>(
        att, woutT, out, ROWS, DIM, INNER, 0);
}